// round 5
// baseline (speedup 1.0000x reference)
#include <cuda_runtime.h>
#include <cuda_fp16.h>

#define SPB 12           // samples per block (1 warp per sample; warp pairs share MLP weights)
#define THREADS 384

// ---- warp-uniform weight vectors in constant memory (ULDC path, zero l1tex) ----
__constant__ float cWE[64];
__constant__ float cATT[64];
__constant__ float cWE4[4];    // g2_we (3 used, [3]=0)
__constant__ float cATT4[4];   // g2_att (3 used, [3]=0)

// ---- weight offsets in shared (floats) ----
enum {
  EW1=0, EB1=192, EW2P=256, EB2P=4352, EW3P=4416, EB3=4672,
  G1WL=4676, G1BL=4868, G1WR=4932, G1BR=5124, G1BIAS=5188,
  G2WLT=5252, G2BL4=5444, G2WRT=5448, G2BR4=5640, G2BIAS4=5644,
  SKW=5648, SKB=5660,
  DW1=5664, DB1=5856, DW2H=5920 /*4096 halves = 2048 float slots*/,
  DB2P=7968, DW3P=8032, DB3=8288,
  WTOT=8292
};
// ---- per-sample scratch offsets (floats) ----
// U region: SA=[0,512) | SLATP=[512,560) | SXL=[0,544) SXR=[544,1088)  (disjoint lifetimes)
enum {
  SA=0, SLATP=512, SXL=0, SXR=544,
  SEAT=1088, SMSK=1152, SALPHA=1216,
  SLAT=1280, SVIS=1312, SCOMB=1344, SXL2=1376, SXR2=1408, SX=1440,
  SPER=1456
};

#define SMEM_FLOATS (WTOT + SPB*SPER)
#define SMEM_BYTES  (SMEM_FLOATS*4)   // 103,056 bytes -> 2 blocks/SM

struct KParams {
  const float* x;
  const float* w[28];
  int B;
};

extern __shared__ float smem[];

__device__ __forceinline__ void cpy(float* dst, const float* src, int n, int tid) {
  for (int i = tid; i < n; i += THREADS) dst[i] = src[i];
}

__device__ __forceinline__ float lrelu(float h) {
  return fmaxf(h, 0.f) + 0.2f*fminf(h, 0.f);
}

__device__ __forceinline__ float4 relu4(float4 a) {
  return make_float4(fmaxf(a.x,0.f), fmaxf(a.y,0.f), fmaxf(a.z,0.f), fmaxf(a.w,0.f));
}

// shared epilogue: relu accumulators, fused (64->3) projection partials, pair barrier.
__device__ __forceinline__ void mlp_epilogue(
    float4 A0, float4 A1, float4 A2, float4 A3,
    float* scp, const float* __restrict__ W3p,
    int t, int h, int barid)
{
  const int cg = t & 7, ng = t >> 4;
  A0 = relu4(A0); A1 = relu4(A1); A2 = relu4(A2); A3 = relu4(A3);

  const int p0i = h*32 + cg*4;
  float4 E0 = *(const float4*)&W3p[(p0i+0)*4];
  float4 E1 = *(const float4*)&W3p[(p0i+1)*4];
  float4 E2 = *(const float4*)&W3p[(p0i+2)*4];
  float4 E3 = *(const float4*)&W3p[(p0i+3)*4];

  float4 p0, p1, p2;
  p0.x = fmaf(A0.x,E0.x, fmaf(A1.x,E1.x, fmaf(A2.x,E2.x, A3.x*E3.x)));
  p0.y = fmaf(A0.y,E0.x, fmaf(A1.y,E1.x, fmaf(A2.y,E2.x, A3.y*E3.x)));
  p0.z = fmaf(A0.z,E0.x, fmaf(A1.z,E1.x, fmaf(A2.z,E2.x, A3.z*E3.x)));
  p0.w = fmaf(A0.w,E0.x, fmaf(A1.w,E1.x, fmaf(A2.w,E2.x, A3.w*E3.x)));
  p1.x = fmaf(A0.x,E0.y, fmaf(A1.x,E1.y, fmaf(A2.x,E2.y, A3.x*E3.y)));
  p1.y = fmaf(A0.y,E0.y, fmaf(A1.y,E1.y, fmaf(A2.y,E2.y, A3.y*E3.y)));
  p1.z = fmaf(A0.z,E0.y, fmaf(A1.z,E1.y, fmaf(A2.z,E2.y, A3.z*E3.y)));
  p1.w = fmaf(A0.w,E0.y, fmaf(A1.w,E1.y, fmaf(A2.w,E2.y, A3.w*E3.y)));
  p2.x = fmaf(A0.x,E0.z, fmaf(A1.x,E1.z, fmaf(A2.x,E2.z, A3.x*E3.z)));
  p2.y = fmaf(A0.y,E0.z, fmaf(A1.y,E1.z, fmaf(A2.y,E2.z, A3.y*E3.z)));
  p2.z = fmaf(A0.z,E0.z, fmaf(A1.z,E1.z, fmaf(A2.z,E2.z, A3.z*E3.z)));
  p2.w = fmaf(A0.w,E0.z, fmaf(A1.w,E1.z, fmaf(A2.w,E2.z, A3.w*E3.z)));

#pragma unroll
  for (int m = 1; m <= 4; m <<= 1) {
    p0.x += __shfl_xor_sync(0xffffffffu, p0.x, m);
    p0.y += __shfl_xor_sync(0xffffffffu, p0.y, m);
    p0.z += __shfl_xor_sync(0xffffffffu, p0.z, m);
    p0.w += __shfl_xor_sync(0xffffffffu, p0.w, m);
    p1.x += __shfl_xor_sync(0xffffffffu, p1.x, m);
    p1.y += __shfl_xor_sync(0xffffffffu, p1.y, m);
    p1.z += __shfl_xor_sync(0xffffffffu, p1.z, m);
    p1.w += __shfl_xor_sync(0xffffffffu, p1.w, m);
    p2.x += __shfl_xor_sync(0xffffffffu, p2.x, m);
    p2.y += __shfl_xor_sync(0xffffffffu, p2.y, m);
    p2.z += __shfl_xor_sync(0xffffffffu, p2.z, m);
    p2.w += __shfl_xor_sync(0xffffffffu, p2.w, m);
  }
  if (cg == 0) {
    float* d = scp + SLATP + h*24 + (4*ng)*3;
    d[0]  = p0.x; d[1]  = p1.x; d[2]  = p2.x;
    d[3]  = p0.y; d[4]  = p1.y; d[5]  = p2.y;
    d[6]  = p0.z; d[7]  = p1.z; d[8]  = p2.z;
    d[9]  = p0.w; d[10] = p1.w; d[11] = p2.w;
  }
  asm volatile("bar.sync %0, 64;" :: "r"(barid) : "memory");
}

// Encoder: fp32 paired 8x64 @ 64x64 + relu + fused 64->3 partials.
__device__ __forceinline__ void mlp64_pair_f32(
    const float* __restrict__ inA, const float* __restrict__ inB,
    float* scA, float* scB,
    const float* __restrict__ Wp, const float* __restrict__ bp,
    const float* __restrict__ W3p,
    int t, int h, int barid)
{
  const int cg = t & 7, sh = (t >> 3) & 1, ng = t >> 4;
  const float* in = sh ? inB : inA;
  float* scp = sh ? scB : scA;
  const float* wp = Wp + h*32 + cg*4;
  float4 b4 = *(const float4*)&bp[h*32 + cg*4];
  float4 A0 = make_float4(b4.x, b4.x, b4.x, b4.x);
  float4 A1 = make_float4(b4.y, b4.y, b4.y, b4.y);
  float4 A2 = make_float4(b4.z, b4.z, b4.z, b4.z);
  float4 A3 = make_float4(b4.w, b4.w, b4.w, b4.w);
  const float* ap = in + 4*ng;
#pragma unroll 8
  for (int k = 0; k < 64; k++) {
    float4 av = *(const float4*)&ap[k*8];
    float4 wv = *(const float4*)&wp[k*64];
    A0.x = fmaf(wv.x, av.x, A0.x); A0.y = fmaf(wv.x, av.y, A0.y);
    A0.z = fmaf(wv.x, av.z, A0.z); A0.w = fmaf(wv.x, av.w, A0.w);
    A1.x = fmaf(wv.y, av.x, A1.x); A1.y = fmaf(wv.y, av.y, A1.y);
    A1.z = fmaf(wv.y, av.z, A1.z); A1.w = fmaf(wv.y, av.w, A1.w);
    A2.x = fmaf(wv.z, av.x, A2.x); A2.y = fmaf(wv.z, av.y, A2.y);
    A2.z = fmaf(wv.z, av.z, A2.z); A2.w = fmaf(wv.z, av.w, A2.w);
    A3.x = fmaf(wv.w, av.x, A3.x); A3.y = fmaf(wv.w, av.y, A3.y);
    A3.z = fmaf(wv.w, av.z, A3.z); A3.w = fmaf(wv.w, av.w, A3.w);
  }
  mlp_epilogue(A0, A1, A2, A3, scp, W3p, t, h, barid);
}

// Decoder: half-precision storage (half2 loads, fp32 accumulate).
// Activations: half [k][8 nodes] rows (16B). Weights: half [k][64].
__device__ __forceinline__ void mlp64_pair_f16(
    const __half* __restrict__ inA, const __half* __restrict__ inB,
    float* scA, float* scB,
    const __half* __restrict__ Wh, const float* __restrict__ bp,
    const float* __restrict__ W3p,
    int t, int h, int barid)
{
  const int cg = t & 7, sh = (t >> 3) & 1, ng = t >> 4;
  const __half* in = sh ? inB : inA;
  float* scp = sh ? scB : scA;
  const __half* wp = Wh + h*32 + cg*4;
  float4 b4 = *(const float4*)&bp[h*32 + cg*4];
  float4 A0 = make_float4(b4.x, b4.x, b4.x, b4.x);
  float4 A1 = make_float4(b4.y, b4.y, b4.y, b4.y);
  float4 A2 = make_float4(b4.z, b4.z, b4.z, b4.z);
  float4 A3 = make_float4(b4.w, b4.w, b4.w, b4.w);
  const __half* ap = in + 4*ng;
#pragma unroll 8
  for (int k = 0; k < 64; k++) {
    uint2 au = *(const uint2*)(ap + k*8);
    uint2 wu = *(const uint2*)(wp + k*64);
    float2 a01 = __half22float2(*(const __half2*)&au.x);
    float2 a23 = __half22float2(*(const __half2*)&au.y);
    float2 w01 = __half22float2(*(const __half2*)&wu.x);
    float2 w23 = __half22float2(*(const __half2*)&wu.y);
    A0.x = fmaf(w01.x, a01.x, A0.x); A0.y = fmaf(w01.x, a01.y, A0.y);
    A0.z = fmaf(w01.x, a23.x, A0.z); A0.w = fmaf(w01.x, a23.y, A0.w);
    A1.x = fmaf(w01.y, a01.x, A1.x); A1.y = fmaf(w01.y, a01.y, A1.y);
    A1.z = fmaf(w01.y, a23.x, A1.z); A1.w = fmaf(w01.y, a23.y, A1.w);
    A2.x = fmaf(w23.x, a01.x, A2.x); A2.y = fmaf(w23.x, a01.y, A2.y);
    A2.z = fmaf(w23.x, a23.x, A2.z); A2.w = fmaf(w23.x, a23.y, A2.w);
    A3.x = fmaf(w23.y, a01.x, A3.x); A3.y = fmaf(w23.y, a01.y, A3.y);
    A3.z = fmaf(w23.y, a23.x, A3.z); A3.w = fmaf(w23.y, a23.y, A3.w);
  }
  mlp_epilogue(A0, A1, A2, A3, scp, W3p, t, h, barid);
}

__global__ __launch_bounds__(THREADS, 2)
void gae5_kernel(KParams kp, float* __restrict__ out)
{
  float* ws = smem;
  const int tid = threadIdx.x;

  // ================= stage weights =================
  cpy(ws+EW1, kp.w[0], 192, tid); cpy(ws+EB1, kp.w[1], 64, tid);
  cpy(ws+EW2P, kp.w[2], 4096, tid);
  cpy(ws+EB2P, kp.w[3], 64, tid);
  { const float* w4 = kp.w[4];
    for (int i = tid; i < 256; i += THREADS) {
      int c = i >> 2, l = i & 3;
      ws[EW3P + i] = (l < 3) ? w4[c*3 + l] : 0.f;
    } }
  if (tid < 4) ws[EB3+tid] = (tid < 3) ? kp.w[5][tid] : 0.f;
  cpy(ws+G1WL, kp.w[6], 192, tid);  cpy(ws+G1BL, kp.w[7], 64, tid);
  cpy(ws+G1WR, kp.w[8], 192, tid);  cpy(ws+G1BR, kp.w[9], 64, tid);
  cpy(ws+G1BIAS, kp.w[12], 64, tid);
  { const float* wl = kp.w[13]; const float* wr = kp.w[15];
    for (int i = tid; i < 192; i += THREADS) {
      int k = i / 3, l = i - k*3;
      ws[G2WLT + l*64 + k] = wl[i];
      ws[G2WRT + l*64 + k] = wr[i];
    } }
  if (tid < 4) {
    ws[G2BL4 + tid]   = (tid < 3) ? kp.w[14][tid] : 0.f;
    ws[G2BR4 + tid]   = (tid < 3) ? kp.w[16][tid] : 0.f;
    ws[G2BIAS4 + tid] = (tid < 3) ? kp.w[19][tid] : 0.f;
  }
  if (tid < 12) ws[SKW+tid] = (tid < 9) ? kp.w[20][tid] : 0.f;
  if (tid < 4)  ws[SKB+tid] = (tid < 3) ? kp.w[21][tid] : 0.f;
  cpy(ws+DW1, kp.w[22], 192, tid); cpy(ws+DB1, kp.w[23], 64, tid);
  { const float* src = kp.w[24];
    __half* dsth = (__half*)(ws + DW2H);
    for (int i = tid; i < 4096; i += THREADS) dsth[i] = __float2half_rn(src[i]);
  }
  cpy(ws+DB2P, kp.w[25], 64, tid);
  { const float* w26 = kp.w[26];
    for (int i = tid; i < 256; i += THREADS) {
      int c = i >> 2, l = i & 3;
      ws[DW3P + i] = (l < 3) ? w26[c*3 + l] : 0.f;
    } }
  if (tid < 4) ws[DB3+tid] = (tid < 3) ? kp.w[27][tid] : 0.f;

  const int g = tid >> 5;
  const int t = tid & 31;
  const int h = g & 1;
  const int barid = (g >> 1) + 1;
  float* sc  = smem + WTOT + g*SPER;
  float* scA = smem + WTOT + (g & ~1)*SPER;
  float* scB = scA + SPER;
  const int Btot = kp.B;
  const int s = blockIdx.x*SPB + g;
  const bool valid = (s < Btot);
  const int sl = valid ? s : (Btot - 1);

  if (t < 8) sc[SX + t] = kp.x[sl*8 + t];
  __syncthreads();

  const int n3 = t / 3, l3 = t - n3*3;

  // ================= encoder L1 (3->64), layout [c][n] stride 8 =================
  {
    float wn1 = ws[EW1+64+t],    wx1 = ws[EW1+128+t],    bb1 = ws[EB1+t];
    float wn2 = ws[EW1+64+t+32], wx2 = ws[EW1+128+t+32], bb2 = ws[EB1+t+32];
    float va[8], vb[8];
#pragma unroll
    for (int n = 0; n < 8; n++) {
      float xn = sc[SX + n];
      va[n] = fmaxf(fmaf(xn, wx1, fmaf((float)n, wn1, bb1)), 0.f);
      vb[n] = fmaxf(fmaf(xn, wx2, fmaf((float)n, wn2, bb2)), 0.f);
    }
    *(float4*)&sc[SA + t*8]          = make_float4(va[0],va[1],va[2],va[3]);
    *(float4*)&sc[SA + t*8 + 4]      = make_float4(va[4],va[5],va[6],va[7]);
    *(float4*)&sc[SA + (t+32)*8]     = make_float4(vb[0],vb[1],vb[2],vb[3]);
    *(float4*)&sc[SA + (t+32)*8 + 4] = make_float4(vb[4],vb[5],vb[6],vb[7]);
  }
  asm volatile("bar.sync %0, 64;" :: "r"(barid) : "memory");

  // ================= encoder L2 (64x64, paired, fp32) + fused L3 partials ======
  mlp64_pair_f32(scA + SA, scB + SA, scA, scB, ws + EW2P, ws + EB2P, ws + EW3P,
                 t, h, barid);

  if (t < 24)
    sc[SLAT + n3*4 + l3] = sc[SLATP + t] + sc[SLATP + 24 + t] + ws[EB3 + l3];
  __syncwarp();

  // ================= normalize -> vis  (lane = l*8+n) =================
  {
    int ln_l = t >> 3, ln_n = t & 7;
    float v = sc[SLAT + ln_n*4 + ((ln_l < 3) ? ln_l : 0)];
    float sm = v;
    sm += __shfl_xor_sync(0xffffffffu, sm, 1);
    sm += __shfl_xor_sync(0xffffffffu, sm, 2);
    sm += __shfl_xor_sync(0xffffffffu, sm, 4);
    float c = v - sm*0.125f;
    float vv = c*c;
    vv += __shfl_xor_sync(0xffffffffu, vv, 1);
    vv += __shfl_xor_sync(0xffffffffu, vv, 2);
    vv += __shfl_xor_sync(0xffffffffu, vv, 4);
    float inv = 1.f / (sqrtf(vv * (1.f/7.f)) + 1e-8f);
    float visv = c*inv;
    if (t < 24) {
      sc[SVIS + ln_n*4 + ln_l] = visv;
      if (valid) {
        out[2*Btot*24 + s*24 + ln_n*3 + ln_l] = visv;    // vis
        float xpv = (l3 == 0) ? 0.f : ((l3 == 1) ? (float)n3 : sc[SX + n3]);
        out[s*24 + t] = xpv;                             // xp
      }
    }
  }
  __syncwarp();

  // ================= Gabriel graph (2 pairs per lane) =================
  {
    float4 Pv[8];
#pragma unroll
    for (int n = 0; n < 8; n++) Pv[n] = *(const float4*)&sc[SVIS + n*4];
    int i0 = t >> 3, j0 = t & 7;
    int i1 = (t + 32) >> 3;
    float4 pi0 = Pv[i0], pj0 = Pv[j0], pi1 = Pv[i1];
    float a0, d0, a1, d1;
    {
      float mx=(pi0.x+pj0.x)*0.5f, my=(pi0.y+pj0.y)*0.5f, mz=(pi0.z+pj0.z)*0.5f;
      float rx=pi0.x-mx, ry=pi0.y-my, rz=pi0.z-mz;
      float r2 = rx*rx+ry*ry+rz*rz;
      bool viol = false;
#pragma unroll
      for (int k = 0; k < 8; k++) {
        float ex=Pv[k].x-mx, ey=Pv[k].y-my, ez=Pv[k].z-mz;
        float d2 = ex*ex+ey*ey+ez*ez;
        viol |= (k != i0) && (k != j0) && (d2 < r2);
      }
      a0 = (!viol && (i0 != j0)) ? 1.f : 0.f;
      float dx=pi0.x-pj0.x, dy=pi0.y-pj0.y, dz=pi0.z-pj0.z;
      d0 = sqrtf(dx*dx+dy*dy+dz*dz + 1e-30f);
    }
    {
      float mx=(pi1.x+pj0.x)*0.5f, my=(pi1.y+pj0.y)*0.5f, mz=(pi1.z+pj0.z)*0.5f;
      float rx=pi1.x-mx, ry=pi1.y-my, rz=pi1.z-mz;
      float r2 = rx*rx+ry*ry+rz*rz;
      bool viol = false;
#pragma unroll
      for (int k = 0; k < 8; k++) {
        float ex=Pv[k].x-mx, ey=Pv[k].y-my, ez=Pv[k].z-mz;
        float d2 = ex*ex+ey*ey+ez*ez;
        viol |= (k != i1) && (k != j0) && (d2 < r2);
      }
      a1 = (!viol && (i1 != j0)) ? 1.f : 0.f;
      float dx=pi1.x-pj0.x, dy=pi1.y-pj0.y, dz=pi1.z-pj0.z;
      d1 = sqrtf(dx*dx+dy*dy+dz*dz + 1e-30f);
    }
    float as = a0 + a1, ds = a0*d0 + a1*d1;
#pragma unroll
    for (int m = 16; m; m >>= 1) {
      as += __shfl_xor_sync(0xffffffffu, as, m);
      ds += __shfl_xor_sync(0xffffffffu, ds, m);
    }
    float ma = ds / fmaxf(as, 1.f);
    sc[SEAT + t]      = (i0 == j0) ? ma  : d0;
    sc[SEAT + t + 32] = (i1 == j0) ? ma  : d1;
    sc[SMSK + t]      = (i0 == j0) ? 1.f : a0;
    sc[SMSK + t + 32] = (i1 == j0) ? 1.f : a1;
    if (valid) {
      out[3*Btot*24 + s*64 + t]      = a0;
      out[3*Btot*24 + s*64 + t + 32] = a1;
    }
  }

  // ================= GAT1 linear (3->64 xl, xr)  [n][c] stride 68 =================
  {
    float wl0a=ws[G1WL+t],    wl1a=ws[G1WL+64+t],    wl2a=ws[G1WL+128+t],    bla=ws[G1BL+t];
    float wl0b=ws[G1WL+t+32], wl1b=ws[G1WL+64+t+32], wl2b=ws[G1WL+128+t+32], blb=ws[G1BL+t+32];
    float wr0a=ws[G1WR+t],    wr1a=ws[G1WR+64+t],    wr2a=ws[G1WR+128+t],    bra=ws[G1BR+t];
    float wr0b=ws[G1WR+t+32], wr1b=ws[G1WR+64+t+32], wr2b=ws[G1WR+128+t+32], brb=ws[G1BR+t+32];
#pragma unroll
    for (int n = 0; n < 8; n++) {
      float4 la = *(const float4*)&sc[SLAT + n*4];
      sc[SXL + n*68 + t]      = fmaf(la.x, wl0a, fmaf(la.y, wl1a, fmaf(la.z, wl2a, bla)));
      sc[SXL + n*68 + t + 32] = fmaf(la.x, wl0b, fmaf(la.y, wl1b, fmaf(la.z, wl2b, blb)));
      sc[SXR + n*68 + t]      = fmaf(la.x, wr0a, fmaf(la.y, wr1a, fmaf(la.z, wr2a, bra)));
      sc[SXR + n*68 + t + 32] = fmaf(la.x, wr0b, fmaf(la.y, wr1b, fmaf(la.z, wr2b, brb)));
    }
  }
  __syncwarp();

  // ================= GAT1 edge scores + softmax (pairs 2t, 2t+1) =================
  {
    const int i = t >> 2;
    const int jj = (t & 3) * 2;
    const float* xr = sc + SXR + i*68;
    const float* xa = sc + SXL + jj*68;
    float2 ea = *(const float2*)&sc[SEAT + 2*t];
    float2 mk = *(const float2*)&sc[SMSK + 2*t];
    float acc0 = 0.f, acc1 = 0.f;
#pragma unroll 8
    for (int c = 0; c < 64; c += 4) {
      float4 r  = *(const float4*)&xr[c];
      float4 l0 = *(const float4*)&xa[c];
      float4 l1 = *(const float4*)&xa[c + 68];
      float we0=cWE[c], we1=cWE[c+1], we2=cWE[c+2], we3=cWE[c+3];   // ULDC
      float at0=cATT[c], at1=cATT[c+1], at2=cATT[c+2], at3=cATT[c+3];
      acc0 = fmaf(lrelu(fmaf(ea.x, we0, r.x) + l0.x), at0, acc0);
      acc1 = fmaf(lrelu(fmaf(ea.y, we0, r.x) + l1.x), at0, acc1);
      acc0 = fmaf(lrelu(fmaf(ea.x, we1, r.y) + l0.y), at1, acc0);
      acc1 = fmaf(lrelu(fmaf(ea.y, we1, r.y) + l1.y), at1, acc1);
      acc0 = fmaf(lrelu(fmaf(ea.x, we2, r.z) + l0.z), at2, acc0);
      acc1 = fmaf(lrelu(fmaf(ea.y, we2, r.z) + l1.z), at2, acc1);
      acc0 = fmaf(lrelu(fmaf(ea.x, we3, r.w) + l0.w), at3, acc0);
      acc1 = fmaf(lrelu(fmaf(ea.y, we3, r.w) + l1.w), at3, acc1);
    }
    float e0 = (mk.x != 0.f) ? acc0 : -1e30f;
    float e1 = (mk.y != 0.f) ? acc1 : -1e30f;
    float m = fmaxf(e0, e1);
    m = fmaxf(m, __shfl_xor_sync(0xffffffffu, m, 1));
    m = fmaxf(m, __shfl_xor_sync(0xffffffffu, m, 2));
    float x0 = __expf(e0 - m), x1 = __expf(e1 - m);
    float sden = x0 + x1;
    sden += __shfl_xor_sync(0xffffffffu, sden, 1);
    sden += __shfl_xor_sync(0xffffffffu, sden, 2);
    float inv = 1.f / sden;
    *(float2*)&sc[SALPHA + 2*t] = make_float2(x0*inv*mk.x, x1*inv*mk.y);
  }
  __syncwarp();

  // ================= GAT1 aggregation -> h1 (into SXR), relu =================
  {
    float acc1[8], acc2[8];
    float b1 = ws[G1BIAS + t], b2 = ws[G1BIAS + t + 32];
#pragma unroll
    for (int i = 0; i < 8; i++) { acc1[i] = b1; acc2[i] = b2; }
#pragma unroll
    for (int j = 0; j < 8; j += 2) {
      float xv1a = sc[SXL + j*68 + t],       xv2a = sc[SXL + j*68 + t + 32];
      float xv1b = sc[SXL + (j+1)*68 + t],   xv2b = sc[SXL + (j+1)*68 + t + 32];
#pragma unroll
      for (int i = 0; i < 8; i++) {
        float2 al = *(const float2*)&sc[SALPHA + i*8 + j];
        acc1[i] = fmaf(al.x, xv1a, fmaf(al.y, xv1b, acc1[i]));
        acc2[i] = fmaf(al.x, xv2a, fmaf(al.y, xv2b, acc2[i]));
      }
    }
    __syncwarp();
#pragma unroll
    for (int i = 0; i < 8; i++) {
      sc[SXR + i*68 + t]      = fmaxf(acc1[i], 0.f);
      sc[SXR + i*68 + t + 32] = fmaxf(acc2[i], 0.f);
    }
  }
  __syncwarp();

  // ================= GAT2 linear (64->3 xl2, xr2) =================
  if (t < 24) {
    float a1 = ws[G2BL4 + l3], a2 = ws[G2BR4 + l3];
    const float* h1p = sc + SXR + n3*68;
#pragma unroll
    for (int c = 0; c < 64; c += 4) {
      float4 hh = *(const float4*)&h1p[c];
      float4 wl = *(const float4*)&ws[G2WLT + l3*64 + c];
      float4 wr = *(const float4*)&ws[G2WRT + l3*64 + c];
      a1 = fmaf(hh.x, wl.x, fmaf(hh.y, wl.y, fmaf(hh.z, wl.z, fmaf(hh.w, wl.w, a1))));
      a2 = fmaf(hh.x, wr.x, fmaf(hh.y, wr.y, fmaf(hh.z, wr.z, fmaf(hh.w, wr.w, a2))));
    }
    sc[SXL2 + n3*4 + l3] = a1;
    sc[SXR2 + n3*4 + l3] = a2;
  }
  __syncwarp();

  // ================= GAT2 edge scores + softmax =================
  {
    const int i = t >> 2;
    const int jj = (t & 3) * 2;
    float4 r   = *(const float4*)&sc[SXR2 + i*4];
    float4 l0  = *(const float4*)&sc[SXL2 + jj*4];
    float4 l1  = *(const float4*)&sc[SXL2 + (jj+1)*4];
    float2 ea = *(const float2*)&sc[SEAT + 2*t];
    float2 mk = *(const float2*)&sc[SMSK + 2*t];
    float acc0 = 0.f, acc1 = 0.f;
    acc0 = fmaf(lrelu(fmaf(ea.x, cWE4[0], r.x) + l0.x), cATT4[0], acc0);
    acc1 = fmaf(lrelu(fmaf(ea.y, cWE4[0], r.x) + l1.x), cATT4[0], acc1);
    acc0 = fmaf(lrelu(fmaf(ea.x, cWE4[1], r.y) + l0.y), cATT4[1], acc0);
    acc1 = fmaf(lrelu(fmaf(ea.y, cWE4[1], r.y) + l1.y), cATT4[1], acc1);
    acc0 = fmaf(lrelu(fmaf(ea.x, cWE4[2], r.z) + l0.z), cATT4[2], acc0);
    acc1 = fmaf(lrelu(fmaf(ea.y, cWE4[2], r.z) + l1.z), cATT4[2], acc1);
    float e0 = (mk.x != 0.f) ? acc0 : -1e30f;
    float e1 = (mk.y != 0.f) ? acc1 : -1e30f;
    float m = fmaxf(e0, e1);
    m = fmaxf(m, __shfl_xor_sync(0xffffffffu, m, 1));
    m = fmaxf(m, __shfl_xor_sync(0xffffffffu, m, 2));
    float x0 = __expf(e0 - m), x1 = __expf(e1 - m);
    float sden = x0 + x1;
    sden += __shfl_xor_sync(0xffffffffu, sden, 1);
    sden += __shfl_xor_sync(0xffffffffu, sden, 2);
    float inv = 1.f / sden;
    *(float2*)&sc[SALPHA + 2*t] = make_float2(x0*inv*mk.x, x1*inv*mk.y);
  }
  __syncwarp();

  // ================= GAT2 aggregation + skip -> combined =================
  if (t < 24) {
    float acc = ws[G2BIAS4 + l3];
#pragma unroll
    for (int j = 0; j < 8; j++)
      acc = fmaf(sc[SALPHA + n3*8 + j], sc[SXL2 + j*4 + l3], acc);
    float4 la = *(const float4*)&sc[SLAT + n3*4];
    acc += fmaf(la.x, ws[SKW + l3],
           fmaf(la.y, ws[SKW + 3 + l3],
           fmaf(la.z, ws[SKW + 6 + l3], ws[SKB + l3])));
    sc[SCOMB + n3*4 + l3] = acc;
  }
  __syncwarp();

  // ================= decoder L1 (3->64) -> half rows [ch][8n] =================
  {
    float w0a=ws[DW1+t],    w1a=ws[DW1+64+t],    w2a=ws[DW1+128+t],    ba=ws[DB1+t];
    float w0b=ws[DW1+t+32], w1b=ws[DW1+64+t+32], w2b=ws[DW1+128+t+32], bb=ws[DB1+t+32];
    float va[8], vb[8];
#pragma unroll
    for (int n = 0; n < 8; n++) {
      float4 cm = *(const float4*)&sc[SCOMB + n*4];
      va[n] = fmaxf(fmaf(cm.x, w0a, fmaf(cm.y, w1a, fmaf(cm.z, w2a, ba))), 0.f);
      vb[n] = fmaxf(fmaf(cm.x, w0b, fmaf(cm.y, w1b, fmaf(cm.z, w2b, bb))), 0.f);
    }
    __half2* aH = (__half2*)(sc + SA);   // row ch: 4 half2 (16B)
    aH[t*4 + 0]      = __floats2half2_rn(va[0], va[1]);
    aH[t*4 + 1]      = __floats2half2_rn(va[2], va[3]);
    aH[t*4 + 2]      = __floats2half2_rn(va[4], va[5]);
    aH[t*4 + 3]      = __floats2half2_rn(va[6], va[7]);
    aH[(t+32)*4 + 0] = __floats2half2_rn(vb[0], vb[1]);
    aH[(t+32)*4 + 1] = __floats2half2_rn(vb[2], vb[3]);
    aH[(t+32)*4 + 2] = __floats2half2_rn(vb[4], vb[5]);
    aH[(t+32)*4 + 3] = __floats2half2_rn(vb[6], vb[7]);
  }
  asm volatile("bar.sync %0, 64;" :: "r"(barid) : "memory");

  // ================= decoder L2 (64x64, paired, fp16 storage) + DW3 partials ====
  mlp64_pair_f16((const __half*)(scA + SA), (const __half*)(scB + SA),
                 scA, scB, (const __half*)(ws + DW2H), ws + DB2P, ws + DW3P,
                 t, h, barid);

  if (valid && t < 24)
    out[Btot*24 + s*24 + t] = sc[SLATP + t] + sc[SLATP + 24 + t] + ws[DB3 + l3];
}

extern "C" void kernel_launch(void* const* d_in, const int* in_sizes, int n_in,
                              void* d_out, int out_size)
{
  (void)n_in; (void)out_size;
  KParams kp;
  kp.x = (const float*)d_in[0];
  for (int i = 0; i < 28; i++) kp.w[i] = (const float*)d_in[i + 1];
  kp.B = in_sizes[0] / 8;

  // warp-uniform weight vectors -> constant memory (D2D async copies; graph-capturable)
  cudaMemcpyToSymbolAsync(cWE,   d_in[11], 64*sizeof(float), 0, cudaMemcpyDeviceToDevice, 0);
  cudaMemcpyToSymbolAsync(cATT,  d_in[12], 64*sizeof(float), 0, cudaMemcpyDeviceToDevice, 0);
  cudaMemcpyToSymbolAsync(cWE4,  d_in[18],  3*sizeof(float), 0, cudaMemcpyDeviceToDevice, 0);
  cudaMemcpyToSymbolAsync(cATT4, d_in[19],  3*sizeof(float), 0, cudaMemcpyDeviceToDevice, 0);

  cudaFuncSetAttribute(gae5_kernel, cudaFuncAttributeMaxDynamicSharedMemorySize, SMEM_BYTES);
  int grid = (kp.B + SPB - 1) / SPB;
  gae5_kernel<<<grid, THREADS, SMEM_BYTES>>>(kp, (float*)d_out);
}

// round 6
// speedup vs baseline: 1.1286x; 1.1286x over previous
#include <cuda_runtime.h>

#define SPB 28           // samples per block (1 warp per sample; warp pairs share MLP weights)
#define THREADS 896      // one block per SM; single shared weight copy

// ---- weight offsets in shared (floats) ----
enum {
  EW1=0, EB1=192, EW2P=256, EB2P=4352, EW3P=4416, EB3=4672,
  G1WL=4676, G1BL=4868, G1WR=4932, G1BR=5124, G1WE=5188, G1ATT=5252, G1BIAS=5316,
  G2WLT=5380, G2BL4=5572, G2WRT=5576, G2BR4=5768,
  G2WE4=5772, G2ATT4=5776, G2BIAS4=5780,
  SKW=5784, SKB=5796,
  DW1=5800, DB1=5992, DW2P=6056, DB2P=10152, DW3P=10216, DB3=10472,
  WTOT=10476
};
// ---- per-sample scratch offsets (floats) ----
// U region: SA=[0,512) | SLATP=[512,560) | SXL=[0,544) SXR=[544,1088)  (disjoint lifetimes)
enum {
  SA=0, SLATP=512, SXL=0, SXR=544,
  SEAT=1088, SMSK=1152, SALPHA=1216,
  SLAT=1280, SVIS=1312, SCOMB=1344, SXL2=1376, SXR2=1408, SX=1440,
  SPER=1456
};

#define SMEM_FLOATS (WTOT + SPB*SPER)
#define SMEM_BYTES  (SMEM_FLOATS*4)   // 204,992 bytes -> 1 block/SM, 28 warps

struct KParams {
  const float* x;
  const float* w[28];
  int B;
};

extern __shared__ float smem[];

__device__ __forceinline__ void cpy(float* dst, const float* src, int n, int tid) {
  for (int i = tid; i < n; i += THREADS) dst[i] = src[i];
}

__device__ __forceinline__ float lrelu(float h) {
  return fmaxf(h, 0.f) + 0.2f*fminf(h, 0.f);
}

__device__ __forceinline__ float4 relu4(float4 a) {
  return make_float4(fmaxf(a.x,0.f), fmaxf(a.y,0.f), fmaxf(a.z,0.f), fmaxf(a.w,0.f));
}

// Paired 8x64 @ 64x64 + relu + fused (64->3) projection partials.
// Warp pair: h = warp&1 selects channel half [h*32, h*32+32).
// Thread: cg=t&7 (4 channels), sh=(t>>3)&1 (sample), ng=t>>4 (nodes 4ng..4ng+3).
__device__ __forceinline__ void mlp64_pair_partial(
    const float* __restrict__ inA, const float* __restrict__ inB,
    float* scA, float* scB,
    const float* __restrict__ Wp, const float* __restrict__ bp,
    const float* __restrict__ W3p,
    int t, int h, int barid)
{
  const int cg = t & 7, sh = (t >> 3) & 1, ng = t >> 4;
  const float* in = sh ? inB : inA;
  float* scp = sh ? scB : scA;
  const float* wp = Wp + h*32 + cg*4;
  float4 b4 = *(const float4*)&bp[h*32 + cg*4];
  float4 A0 = make_float4(b4.x, b4.x, b4.x, b4.x);
  float4 A1 = make_float4(b4.y, b4.y, b4.y, b4.y);
  float4 A2 = make_float4(b4.z, b4.z, b4.z, b4.z);
  float4 A3 = make_float4(b4.w, b4.w, b4.w, b4.w);
  const float* ap = in + 4*ng;
#pragma unroll 8
  for (int k = 0; k < 64; k++) {
    float4 av = *(const float4*)&ap[k*8];
    float4 wv = *(const float4*)&wp[k*64];
    A0.x = fmaf(wv.x, av.x, A0.x); A0.y = fmaf(wv.x, av.y, A0.y);
    A0.z = fmaf(wv.x, av.z, A0.z); A0.w = fmaf(wv.x, av.w, A0.w);
    A1.x = fmaf(wv.y, av.x, A1.x); A1.y = fmaf(wv.y, av.y, A1.y);
    A1.z = fmaf(wv.y, av.z, A1.z); A1.w = fmaf(wv.y, av.w, A1.w);
    A2.x = fmaf(wv.z, av.x, A2.x); A2.y = fmaf(wv.z, av.y, A2.y);
    A2.z = fmaf(wv.z, av.z, A2.z); A2.w = fmaf(wv.z, av.w, A2.w);
    A3.x = fmaf(wv.w, av.x, A3.x); A3.y = fmaf(wv.w, av.y, A3.y);
    A3.z = fmaf(wv.w, av.z, A3.z); A3.w = fmaf(wv.w, av.w, A3.w);
  }
  A0 = relu4(A0); A1 = relu4(A1); A2 = relu4(A2); A3 = relu4(A3);

  const int p0i = h*32 + cg*4;
  float4 E0 = *(const float4*)&W3p[(p0i+0)*4];
  float4 E1 = *(const float4*)&W3p[(p0i+1)*4];
  float4 E2 = *(const float4*)&W3p[(p0i+2)*4];
  float4 E3 = *(const float4*)&W3p[(p0i+3)*4];

  float4 p0, p1, p2;
  p0.x = fmaf(A0.x,E0.x, fmaf(A1.x,E1.x, fmaf(A2.x,E2.x, A3.x*E3.x)));
  p0.y = fmaf(A0.y,E0.x, fmaf(A1.y,E1.x, fmaf(A2.y,E2.x, A3.y*E3.x)));
  p0.z = fmaf(A0.z,E0.x, fmaf(A1.z,E1.x, fmaf(A2.z,E2.x, A3.z*E3.x)));
  p0.w = fmaf(A0.w,E0.x, fmaf(A1.w,E1.x, fmaf(A2.w,E2.x, A3.w*E3.x)));
  p1.x = fmaf(A0.x,E0.y, fmaf(A1.x,E1.y, fmaf(A2.x,E2.y, A3.x*E3.y)));
  p1.y = fmaf(A0.y,E0.y, fmaf(A1.y,E1.y, fmaf(A2.y,E2.y, A3.y*E3.y)));
  p1.z = fmaf(A0.z,E0.y, fmaf(A1.z,E1.y, fmaf(A2.z,E2.y, A3.z*E3.y)));
  p1.w = fmaf(A0.w,E0.y, fmaf(A1.w,E1.y, fmaf(A2.w,E2.y, A3.w*E3.y)));
  p2.x = fmaf(A0.x,E0.z, fmaf(A1.x,E1.z, fmaf(A2.x,E2.z, A3.x*E3.z)));
  p2.y = fmaf(A0.y,E0.z, fmaf(A1.y,E1.z, fmaf(A2.y,E2.z, A3.y*E3.z)));
  p2.z = fmaf(A0.z,E0.z, fmaf(A1.z,E1.z, fmaf(A2.z,E2.z, A3.z*E3.z)));
  p2.w = fmaf(A0.w,E0.z, fmaf(A1.w,E1.z, fmaf(A2.w,E2.z, A3.w*E3.z)));

#pragma unroll
  for (int m = 1; m <= 4; m <<= 1) {
    p0.x += __shfl_xor_sync(0xffffffffu, p0.x, m);
    p0.y += __shfl_xor_sync(0xffffffffu, p0.y, m);
    p0.z += __shfl_xor_sync(0xffffffffu, p0.z, m);
    p0.w += __shfl_xor_sync(0xffffffffu, p0.w, m);
    p1.x += __shfl_xor_sync(0xffffffffu, p1.x, m);
    p1.y += __shfl_xor_sync(0xffffffffu, p1.y, m);
    p1.z += __shfl_xor_sync(0xffffffffu, p1.z, m);
    p1.w += __shfl_xor_sync(0xffffffffu, p1.w, m);
    p2.x += __shfl_xor_sync(0xffffffffu, p2.x, m);
    p2.y += __shfl_xor_sync(0xffffffffu, p2.y, m);
    p2.z += __shfl_xor_sync(0xffffffffu, p2.z, m);
    p2.w += __shfl_xor_sync(0xffffffffu, p2.w, m);
  }
  if (cg == 0) {
    float* d = scp + SLATP + h*24 + (4*ng)*3;
    d[0]  = p0.x; d[1]  = p1.x; d[2]  = p2.x;
    d[3]  = p0.y; d[4]  = p1.y; d[5]  = p2.y;
    d[6]  = p0.z; d[7]  = p1.z; d[8]  = p2.z;
    d[9]  = p0.w; d[10] = p1.w; d[11] = p2.w;
  }
  asm volatile("bar.sync %0, 64;" :: "r"(barid) : "memory");
}

__global__ __launch_bounds__(THREADS, 1)
void gae6_kernel(KParams kp, float* __restrict__ out)
{
  float* ws = smem;
  const int tid = threadIdx.x;

  // ================= stage weights =================
  cpy(ws+EW1, kp.w[0], 192, tid); cpy(ws+EB1, kp.w[1], 64, tid);
  cpy(ws+EW2P, kp.w[2], 4096, tid);
  cpy(ws+EB2P, kp.w[3], 64, tid);
  { const float* w4 = kp.w[4];
    for (int i = tid; i < 256; i += THREADS) {
      int c = i >> 2, l = i & 3;
      ws[EW3P + i] = (l < 3) ? w4[c*3 + l] : 0.f;
    } }
  if (tid < 4) ws[EB3+tid] = (tid < 3) ? kp.w[5][tid] : 0.f;
  cpy(ws+G1WL, kp.w[6], 192, tid);  cpy(ws+G1BL, kp.w[7], 64, tid);
  cpy(ws+G1WR, kp.w[8], 192, tid);  cpy(ws+G1BR, kp.w[9], 64, tid);
  cpy(ws+G1WE, kp.w[10], 64, tid);  cpy(ws+G1ATT, kp.w[11], 64, tid);
  cpy(ws+G1BIAS, kp.w[12], 64, tid);
  { const float* wl = kp.w[13]; const float* wr = kp.w[15];
    for (int i = tid; i < 192; i += THREADS) {
      int k = i / 3, l = i - k*3;
      ws[G2WLT + l*64 + k] = wl[i];
      ws[G2WRT + l*64 + k] = wr[i];
    } }
  if (tid < 4) {
    ws[G2BL4 + tid]   = (tid < 3) ? kp.w[14][tid] : 0.f;
    ws[G2BR4 + tid]   = (tid < 3) ? kp.w[16][tid] : 0.f;
    ws[G2WE4 + tid]   = (tid < 3) ? kp.w[17][tid] : 0.f;
    ws[G2ATT4 + tid]  = (tid < 3) ? kp.w[18][tid] : 0.f;
    ws[G2BIAS4 + tid] = (tid < 3) ? kp.w[19][tid] : 0.f;
  }
  if (tid < 12) ws[SKW+tid] = (tid < 9) ? kp.w[20][tid] : 0.f;
  if (tid < 4)  ws[SKB+tid] = (tid < 3) ? kp.w[21][tid] : 0.f;
  cpy(ws+DW1, kp.w[22], 192, tid); cpy(ws+DB1, kp.w[23], 64, tid);
  cpy(ws+DW2P, kp.w[24], 4096, tid);
  cpy(ws+DB2P, kp.w[25], 64, tid);
  { const float* w26 = kp.w[26];
    for (int i = tid; i < 256; i += THREADS) {
      int c = i >> 2, l = i & 3;
      ws[DW3P + i] = (l < 3) ? w26[c*3 + l] : 0.f;
    } }
  if (tid < 4) ws[DB3+tid] = (tid < 3) ? kp.w[27][tid] : 0.f;

  const int g = tid >> 5;
  const int t = tid & 31;
  const int h = g & 1;
  const int barid = (g >> 1) + 1;   // pair ids 1..14; __syncthreads uses 0
  float* sc  = smem + WTOT + g*SPER;
  float* scA = smem + WTOT + (g & ~1)*SPER;
  float* scB = scA + SPER;
  const int Btot = kp.B;
  const int s = blockIdx.x*SPB + g;
  const bool valid = (s < Btot);
  const int sl = valid ? s : (Btot - 1);

  if (t < 8) sc[SX + t] = kp.x[sl*8 + t];
  __syncthreads();

  const int n3 = t / 3, l3 = t - n3*3;    // (node, dim) map for t<24 phases

  // ================= encoder L1 (3->64), layout [c][n] stride 8 =================
  {
    float wn1 = ws[EW1+64+t],    wx1 = ws[EW1+128+t],    bb1 = ws[EB1+t];
    float wn2 = ws[EW1+64+t+32], wx2 = ws[EW1+128+t+32], bb2 = ws[EB1+t+32];
    float va[8], vb[8];
#pragma unroll
    for (int n = 0; n < 8; n++) {
      float xn = sc[SX + n];
      va[n] = fmaxf(fmaf(xn, wx1, fmaf((float)n, wn1, bb1)), 0.f);
      vb[n] = fmaxf(fmaf(xn, wx2, fmaf((float)n, wn2, bb2)), 0.f);
    }
    *(float4*)&sc[SA + t*8]          = make_float4(va[0],va[1],va[2],va[3]);
    *(float4*)&sc[SA + t*8 + 4]      = make_float4(va[4],va[5],va[6],va[7]);
    *(float4*)&sc[SA + (t+32)*8]     = make_float4(vb[0],vb[1],vb[2],vb[3]);
    *(float4*)&sc[SA + (t+32)*8 + 4] = make_float4(vb[4],vb[5],vb[6],vb[7]);
  }
  asm volatile("bar.sync %0, 64;" :: "r"(barid) : "memory");

  // ================= encoder L2 (64x64, paired) + fused L3 partials =================
  mlp64_pair_partial(scA + SA, scB + SA, scA, scB, ws + EW2P, ws + EB2P, ws + EW3P,
                     t, h, barid);

  if (t < 24)
    sc[SLAT + n3*4 + l3] = sc[SLATP + t] + sc[SLATP + 24 + t] + ws[EB3 + l3];
  __syncwarp();

  // ================= normalize -> vis  (lane = l*8+n) =================
  {
    int ln_l = t >> 3, ln_n = t & 7;
    float v = sc[SLAT + ln_n*4 + ((ln_l < 3) ? ln_l : 0)];
    float sm = v;
    sm += __shfl_xor_sync(0xffffffffu, sm, 1);
    sm += __shfl_xor_sync(0xffffffffu, sm, 2);
    sm += __shfl_xor_sync(0xffffffffu, sm, 4);
    float c = v - sm*0.125f;
    float vv = c*c;
    vv += __shfl_xor_sync(0xffffffffu, vv, 1);
    vv += __shfl_xor_sync(0xffffffffu, vv, 2);
    vv += __shfl_xor_sync(0xffffffffu, vv, 4);
    float inv = 1.f / (sqrtf(vv * (1.f/7.f)) + 1e-8f);
    float visv = c*inv;
    if (t < 24) {
      sc[SVIS + ln_n*4 + ln_l] = visv;
      if (valid) {
        out[2*Btot*24 + s*24 + ln_n*3 + ln_l] = visv;    // vis
        float xpv = (l3 == 0) ? 0.f : ((l3 == 1) ? (float)n3 : sc[SX + n3]);
        out[s*24 + t] = xpv;                             // xp
      }
    }
  }
  __syncwarp();

  // ================= Gabriel graph (2 pairs per lane: p=t, p=t+32) =================
  {
    float4 Pv[8];
#pragma unroll
    for (int n = 0; n < 8; n++) Pv[n] = *(const float4*)&sc[SVIS + n*4];
    int i0 = t >> 3, j0 = t & 7;
    int i1 = (t + 32) >> 3;
    float4 pi0 = Pv[i0], pj0 = Pv[j0], pi1 = Pv[i1];
    float a0, d0, a1, d1;
    {
      float mx=(pi0.x+pj0.x)*0.5f, my=(pi0.y+pj0.y)*0.5f, mz=(pi0.z+pj0.z)*0.5f;
      float rx=pi0.x-mx, ry=pi0.y-my, rz=pi0.z-mz;
      float r2 = rx*rx+ry*ry+rz*rz;
      bool viol = false;
#pragma unroll
      for (int k = 0; k < 8; k++) {
        float ex=Pv[k].x-mx, ey=Pv[k].y-my, ez=Pv[k].z-mz;
        float d2 = ex*ex+ey*ey+ez*ez;
        viol |= (k != i0) && (k != j0) && (d2 < r2);
      }
      a0 = (!viol && (i0 != j0)) ? 1.f : 0.f;
      float dx=pi0.x-pj0.x, dy=pi0.y-pj0.y, dz=pi0.z-pj0.z;
      d0 = sqrtf(dx*dx+dy*dy+dz*dz + 1e-30f);
    }
    {
      float mx=(pi1.x+pj0.x)*0.5f, my=(pi1.y+pj0.y)*0.5f, mz=(pi1.z+pj0.z)*0.5f;
      float rx=pi1.x-mx, ry=pi1.y-my, rz=pi1.z-mz;
      float r2 = rx*rx+ry*ry+rz*rz;
      bool viol = false;
#pragma unroll
      for (int k = 0; k < 8; k++) {
        float ex=Pv[k].x-mx, ey=Pv[k].y-my, ez=Pv[k].z-mz;
        float d2 = ex*ex+ey*ey+ez*ez;
        viol |= (k != i1) && (k != j0) && (d2 < r2);
      }
      a1 = (!viol && (i1 != j0)) ? 1.f : 0.f;
      float dx=pi1.x-pj0.x, dy=pi1.y-pj0.y, dz=pi1.z-pj0.z;
      d1 = sqrtf(dx*dx+dy*dy+dz*dz + 1e-30f);
    }
    float as = a0 + a1, ds = a0*d0 + a1*d1;
#pragma unroll
    for (int m = 16; m; m >>= 1) {
      as += __shfl_xor_sync(0xffffffffu, as, m);
      ds += __shfl_xor_sync(0xffffffffu, ds, m);
    }
    float ma = ds / fmaxf(as, 1.f);
    sc[SEAT + t]      = (i0 == j0) ? ma  : d0;
    sc[SEAT + t + 32] = (i1 == j0) ? ma  : d1;
    sc[SMSK + t]      = (i0 == j0) ? 1.f : a0;
    sc[SMSK + t + 32] = (i1 == j0) ? 1.f : a1;
    if (valid) {
      out[3*Btot*24 + s*64 + t]      = a0;
      out[3*Btot*24 + s*64 + t + 32] = a1;
    }
  }

  // ================= GAT1 linear (3->64 xl, xr)  [n][c] stride 68 =================
  {
    float wl0a=ws[G1WL+t],    wl1a=ws[G1WL+64+t],    wl2a=ws[G1WL+128+t],    bla=ws[G1BL+t];
    float wl0b=ws[G1WL+t+32], wl1b=ws[G1WL+64+t+32], wl2b=ws[G1WL+128+t+32], blb=ws[G1BL+t+32];
    float wr0a=ws[G1WR+t],    wr1a=ws[G1WR+64+t],    wr2a=ws[G1WR+128+t],    bra=ws[G1BR+t];
    float wr0b=ws[G1WR+t+32], wr1b=ws[G1WR+64+t+32], wr2b=ws[G1WR+128+t+32], brb=ws[G1BR+t+32];
#pragma unroll
    for (int n = 0; n < 8; n++) {
      float4 la = *(const float4*)&sc[SLAT + n*4];
      sc[SXL + n*68 + t]      = fmaf(la.x, wl0a, fmaf(la.y, wl1a, fmaf(la.z, wl2a, bla)));
      sc[SXL + n*68 + t + 32] = fmaf(la.x, wl0b, fmaf(la.y, wl1b, fmaf(la.z, wl2b, blb)));
      sc[SXR + n*68 + t]      = fmaf(la.x, wr0a, fmaf(la.y, wr1a, fmaf(la.z, wr2a, bra)));
      sc[SXR + n*68 + t + 32] = fmaf(la.x, wr0b, fmaf(la.y, wr1b, fmaf(la.z, wr2b, brb)));
    }
  }
  __syncwarp();

  // ================= GAT1 edge scores + softmax (pairs 2t, 2t+1) =================
  {
    const int i = t >> 2;
    const int jj = (t & 3) * 2;
    const float* xr = sc + SXR + i*68;
    const float* xa = sc + SXL + jj*68;
    float2 ea = *(const float2*)&sc[SEAT + 2*t];
    float2 mk = *(const float2*)&sc[SMSK + 2*t];
    float acc0 = 0.f, acc1 = 0.f;
#pragma unroll 8
    for (int c = 0; c < 64; c += 4) {
      float4 r  = *(const float4*)&xr[c];
      float4 l0 = *(const float4*)&xa[c];
      float4 l1 = *(const float4*)&xa[c + 68];
      float4 we = *(const float4*)&ws[G1WE + c];
      float4 at = *(const float4*)&ws[G1ATT + c];
      acc0 = fmaf(lrelu(fmaf(ea.x, we.x, r.x) + l0.x), at.x, acc0);
      acc1 = fmaf(lrelu(fmaf(ea.y, we.x, r.x) + l1.x), at.x, acc1);
      acc0 = fmaf(lrelu(fmaf(ea.x, we.y, r.y) + l0.y), at.y, acc0);
      acc1 = fmaf(lrelu(fmaf(ea.y, we.y, r.y) + l1.y), at.y, acc1);
      acc0 = fmaf(lrelu(fmaf(ea.x, we.z, r.z) + l0.z), at.z, acc0);
      acc1 = fmaf(lrelu(fmaf(ea.y, we.z, r.z) + l1.z), at.z, acc1);
      acc0 = fmaf(lrelu(fmaf(ea.x, we.w, r.w) + l0.w), at.w, acc0);
      acc1 = fmaf(lrelu(fmaf(ea.y, we.w, r.w) + l1.w), at.w, acc1);
    }
    float e0 = (mk.x != 0.f) ? acc0 : -1e30f;
    float e1 = (mk.y != 0.f) ? acc1 : -1e30f;
    float m = fmaxf(e0, e1);
    m = fmaxf(m, __shfl_xor_sync(0xffffffffu, m, 1));
    m = fmaxf(m, __shfl_xor_sync(0xffffffffu, m, 2));
    float x0 = __expf(e0 - m), x1 = __expf(e1 - m);
    float sden = x0 + x1;
    sden += __shfl_xor_sync(0xffffffffu, sden, 1);
    sden += __shfl_xor_sync(0xffffffffu, sden, 2);
    float inv = 1.f / sden;
    *(float2*)&sc[SALPHA + 2*t] = make_float2(x0*inv*mk.x, x1*inv*mk.y);
  }
  __syncwarp();

  // ================= GAT1 aggregation -> h1 (into SXR), relu =================
  {
    float acc1[8], acc2[8];
    float b1 = ws[G1BIAS + t], b2 = ws[G1BIAS + t + 32];
#pragma unroll
    for (int i = 0; i < 8; i++) { acc1[i] = b1; acc2[i] = b2; }
#pragma unroll
    for (int j = 0; j < 8; j += 2) {
      float xv1a = sc[SXL + j*68 + t],       xv2a = sc[SXL + j*68 + t + 32];
      float xv1b = sc[SXL + (j+1)*68 + t],   xv2b = sc[SXL + (j+1)*68 + t + 32];
#pragma unroll
      for (int i = 0; i < 8; i++) {
        float2 al = *(const float2*)&sc[SALPHA + i*8 + j];
        acc1[i] = fmaf(al.x, xv1a, fmaf(al.y, xv1b, acc1[i]));
        acc2[i] = fmaf(al.x, xv2a, fmaf(al.y, xv2b, acc2[i]));
      }
    }
    __syncwarp();
#pragma unroll
    for (int i = 0; i < 8; i++) {
      sc[SXR + i*68 + t]      = fmaxf(acc1[i], 0.f);
      sc[SXR + i*68 + t + 32] = fmaxf(acc2[i], 0.f);
    }
  }
  __syncwarp();

  // ================= GAT2 linear (64->3 xl2, xr2) =================
  if (t < 24) {
    float a1 = ws[G2BL4 + l3], a2 = ws[G2BR4 + l3];
    const float* h1p = sc + SXR + n3*68;
#pragma unroll
    for (int c = 0; c < 64; c += 4) {
      float4 hh = *(const float4*)&h1p[c];
      float4 wl = *(const float4*)&ws[G2WLT + l3*64 + c];
      float4 wr = *(const float4*)&ws[G2WRT + l3*64 + c];
      a1 = fmaf(hh.x, wl.x, fmaf(hh.y, wl.y, fmaf(hh.z, wl.z, fmaf(hh.w, wl.w, a1))));
      a2 = fmaf(hh.x, wr.x, fmaf(hh.y, wr.y, fmaf(hh.z, wr.z, fmaf(hh.w, wr.w, a2))));
    }
    sc[SXL2 + n3*4 + l3] = a1;
    sc[SXR2 + n3*4 + l3] = a2;
  }
  __syncwarp();

  // ================= GAT2 edge scores + softmax =================
  {
    const int i = t >> 2;
    const int jj = (t & 3) * 2;
    float4 r   = *(const float4*)&sc[SXR2 + i*4];
    float4 l0  = *(const float4*)&sc[SXL2 + jj*4];
    float4 l1  = *(const float4*)&sc[SXL2 + (jj+1)*4];
    float4 we  = *(const float4*)&ws[G2WE4];
    float4 at  = *(const float4*)&ws[G2ATT4];
    float2 ea = *(const float2*)&sc[SEAT + 2*t];
    float2 mk = *(const float2*)&sc[SMSK + 2*t];
    float acc0 = 0.f, acc1 = 0.f;
    acc0 = fmaf(lrelu(fmaf(ea.x, we.x, r.x) + l0.x), at.x, acc0);
    acc1 = fmaf(lrelu(fmaf(ea.y, we.x, r.x) + l1.x), at.x, acc1);
    acc0 = fmaf(lrelu(fmaf(ea.x, we.y, r.y) + l0.y), at.y, acc0);
    acc1 = fmaf(lrelu(fmaf(ea.y, we.y, r.y) + l1.y), at.y, acc1);
    acc0 = fmaf(lrelu(fmaf(ea.x, we.z, r.z) + l0.z), at.z, acc0);
    acc1 = fmaf(lrelu(fmaf(ea.y, we.z, r.z) + l1.z), at.z, acc1);
    float e0 = (mk.x != 0.f) ? acc0 : -1e30f;
    float e1 = (mk.y != 0.f) ? acc1 : -1e30f;
    float m = fmaxf(e0, e1);
    m = fmaxf(m, __shfl_xor_sync(0xffffffffu, m, 1));
    m = fmaxf(m, __shfl_xor_sync(0xffffffffu, m, 2));
    float x0 = __expf(e0 - m), x1 = __expf(e1 - m);
    float sden = x0 + x1;
    sden += __shfl_xor_sync(0xffffffffu, sden, 1);
    sden += __shfl_xor_sync(0xffffffffu, sden, 2);
    float inv = 1.f / sden;
    *(float2*)&sc[SALPHA + 2*t] = make_float2(x0*inv*mk.x, x1*inv*mk.y);
  }
  __syncwarp();

  // ================= GAT2 aggregation + skip -> combined =================
  if (t < 24) {
    float acc = ws[G2BIAS4 + l3];
#pragma unroll
    for (int j = 0; j < 8; j++)
      acc = fmaf(sc[SALPHA + n3*8 + j], sc[SXL2 + j*4 + l3], acc);
    float4 la = *(const float4*)&sc[SLAT + n3*4];
    acc += fmaf(la.x, ws[SKW + l3],
           fmaf(la.y, ws[SKW + 3 + l3],
           fmaf(la.z, ws[SKW + 6 + l3], ws[SKB + l3])));
    sc[SCOMB + n3*4 + l3] = acc;
  }
  __syncwarp();

  // ================= decoder L1 (3->64) =================
  {
    float w0a=ws[DW1+t],    w1a=ws[DW1+64+t],    w2a=ws[DW1+128+t],    ba=ws[DB1+t];
    float w0b=ws[DW1+t+32], w1b=ws[DW1+64+t+32], w2b=ws[DW1+128+t+32], bb=ws[DB1+t+32];
    float va[8], vb[8];
#pragma unroll
    for (int n = 0; n < 8; n++) {
      float4 cm = *(const float4*)&sc[SCOMB + n*4];
      va[n] = fmaxf(fmaf(cm.x, w0a, fmaf(cm.y, w1a, fmaf(cm.z, w2a, ba))), 0.f);
      vb[n] = fmaxf(fmaf(cm.x, w0b, fmaf(cm.y, w1b, fmaf(cm.z, w2b, bb))), 0.f);
    }
    *(float4*)&sc[SA + t*8]          = make_float4(va[0],va[1],va[2],va[3]);
    *(float4*)&sc[SA + t*8 + 4]      = make_float4(va[4],va[5],va[6],va[7]);
    *(float4*)&sc[SA + (t+32)*8]     = make_float4(vb[0],vb[1],vb[2],vb[3]);
    *(float4*)&sc[SA + (t+32)*8 + 4] = make_float4(vb[4],vb[5],vb[6],vb[7]);
  }
  asm volatile("bar.sync %0, 64;" :: "r"(barid) : "memory");

  // ================= decoder L2 (64x64, paired) + fused DW3 partials =================
  mlp64_pair_partial(scA + SA, scB + SA, scA, scB, ws + DW2P, ws + DB2P, ws + DW3P,
                     t, h, barid);

  if (valid && t < 24)
    out[Btot*24 + s*24 + t] = sc[SLATP + t] + sc[SLATP + 24 + t] + ws[DB3 + l3];
}

extern "C" void kernel_launch(void* const* d_in, const int* in_sizes, int n_in,
                              void* d_out, int out_size)
{
  (void)n_in; (void)out_size;
  KParams kp;
  kp.x = (const float*)d_in[0];
  for (int i = 0; i < 28; i++) kp.w[i] = (const float*)d_in[i + 1];
  kp.B = in_sizes[0] / 8;

  cudaFuncSetAttribute(gae6_kernel, cudaFuncAttributeMaxDynamicSharedMemorySize, SMEM_BYTES);
  int grid = (kp.B + SPB - 1) / SPB;
  gae6_kernel<<<grid, THREADS, SMEM_BYTES>>>(kp, (float*)d_out);
}

// round 7
// speedup vs baseline: 1.1334x; 1.0043x over previous
#include <cuda_runtime.h>

#define SPB 32           // samples per block (1 solo warp per sample)
#define THREADS 1024     // one block per SM; single shared weight copy

// ---- weight offsets in shared (floats) ----
enum {
  EW1=0, EB1=192, EW2P=256, EB2P=4352, EW3P=4416, EB3=4672,
  G1WL=4676, G1BL=4868, G1WR=4932, G1BR=5124, G1WE=5188, G1ATT=5252, G1BIAS=5316,
  G2WLT=5380, G2BL4=5572, G2WRT=5576, G2BR4=5768,
  G2WE4=5772, G2ATT4=5776, G2BIAS4=5780,
  SKW=5784, SKB=5796,
  DW1=5800, DB1=5992, DW2P=6056, DB2P=10152, DW3P=10216, DB3=10472,
  WTOT=10476
};
// ---- per-sample scratch offsets (floats) ----
// U region: SA=[0,512) | SLATP=[512,560) | SXL=[0,544) SXR=[544,1088)  (disjoint lifetimes)
enum {
  SA=0, SLATP=512, SXL=0, SXR=544,
  SEAT=1088, SMSK=1152, SALPHA=1216,
  SLAT=1280, SVIS=1312, SCOMB=1344, SXL2=1376, SXR2=1408, SX=1440,
  SPER=1456
};

#define SMEM_FLOATS (WTOT + SPB*SPER)
#define SMEM_BYTES  (SMEM_FLOATS*4)   // 228,272 bytes -> 1 block/SM, 32 warps

struct KParams {
  const float* x;
  const float* w[28];
  int B;
};

extern __shared__ float smem[];

__device__ __forceinline__ void cpy(float* dst, const float* src, int n, int tid) {
  for (int i = tid; i < n; i += THREADS) dst[i] = src[i];
}

__device__ __forceinline__ float lrelu(float h) {
  return fmaxf(h, 0.f) + 0.2f*fminf(h, 0.f);
}

__device__ __forceinline__ float4 relu4(float4 a) {
  return make_float4(fmaxf(a.x,0.f), fmaxf(a.y,0.f), fmaxf(a.z,0.f), fmaxf(a.w,0.f));
}

// Solo-warp 8x64 @ 64x64 + relu + fused (64->3) projection.
// Lane: ng = t&1 (nodes 4ng..4ng+3), cg = t>>1 (channels cg*4..cg*4+3).
// in: [k][n] stride 8. Wp: [k][64]. Leaves latent partial sums (over all 64
// channels) in scp[SLATP + n*3 + l] for n=0..7; caller adds bias after __syncwarp.
__device__ __forceinline__ void mlp64_solo(
    const float* __restrict__ in, float* scp,
    const float* __restrict__ Wp, const float* __restrict__ bp,
    const float* __restrict__ W3p, int t)
{
  const int ng = t & 1, cg = t >> 1;
  float4 b4 = *(const float4*)&bp[cg*4];
  float4 A0 = make_float4(b4.x, b4.x, b4.x, b4.x);
  float4 A1 = make_float4(b4.y, b4.y, b4.y, b4.y);
  float4 A2 = make_float4(b4.z, b4.z, b4.z, b4.z);
  float4 A3 = make_float4(b4.w, b4.w, b4.w, b4.w);
  const float* ap = in + 4*ng;
  const float* wp = Wp + cg*4;
#pragma unroll 8
  for (int k = 0; k < 64; k++) {
    float4 av = *(const float4*)&ap[k*8];
    float4 wv = *(const float4*)&wp[k*64];
    A0.x = fmaf(wv.x, av.x, A0.x); A0.y = fmaf(wv.x, av.y, A0.y);
    A0.z = fmaf(wv.x, av.z, A0.z); A0.w = fmaf(wv.x, av.w, A0.w);
    A1.x = fmaf(wv.y, av.x, A1.x); A1.y = fmaf(wv.y, av.y, A1.y);
    A1.z = fmaf(wv.y, av.z, A1.z); A1.w = fmaf(wv.y, av.w, A1.w);
    A2.x = fmaf(wv.z, av.x, A2.x); A2.y = fmaf(wv.z, av.y, A2.y);
    A2.z = fmaf(wv.z, av.z, A2.z); A2.w = fmaf(wv.z, av.w, A2.w);
    A3.x = fmaf(wv.w, av.x, A3.x); A3.y = fmaf(wv.w, av.y, A3.y);
    A3.z = fmaf(wv.w, av.z, A3.z); A3.w = fmaf(wv.w, av.w, A3.w);
  }
  A0 = relu4(A0); A1 = relu4(A1); A2 = relu4(A2); A3 = relu4(A3);

  const int p0i = cg*4;
  float4 E0 = *(const float4*)&W3p[(p0i+0)*4];
  float4 E1 = *(const float4*)&W3p[(p0i+1)*4];
  float4 E2 = *(const float4*)&W3p[(p0i+2)*4];
  float4 E3 = *(const float4*)&W3p[(p0i+3)*4];

  float4 p0, p1, p2;   // p_l over this lane's 4 nodes
  p0.x = fmaf(A0.x,E0.x, fmaf(A1.x,E1.x, fmaf(A2.x,E2.x, A3.x*E3.x)));
  p0.y = fmaf(A0.y,E0.x, fmaf(A1.y,E1.x, fmaf(A2.y,E2.x, A3.y*E3.x)));
  p0.z = fmaf(A0.z,E0.x, fmaf(A1.z,E1.x, fmaf(A2.z,E2.x, A3.z*E3.x)));
  p0.w = fmaf(A0.w,E0.x, fmaf(A1.w,E1.x, fmaf(A2.w,E2.x, A3.w*E3.x)));
  p1.x = fmaf(A0.x,E0.y, fmaf(A1.x,E1.y, fmaf(A2.x,E2.y, A3.x*E3.y)));
  p1.y = fmaf(A0.y,E0.y, fmaf(A1.y,E1.y, fmaf(A2.y,E2.y, A3.y*E3.y)));
  p1.z = fmaf(A0.z,E0.y, fmaf(A1.z,E1.y, fmaf(A2.z,E2.y, A3.z*E3.y)));
  p1.w = fmaf(A0.w,E0.y, fmaf(A1.w,E1.y, fmaf(A2.w,E2.y, A3.w*E3.y)));
  p2.x = fmaf(A0.x,E0.z, fmaf(A1.x,E1.z, fmaf(A2.x,E2.z, A3.x*E3.z)));
  p2.y = fmaf(A0.y,E0.z, fmaf(A1.y,E1.z, fmaf(A2.y,E2.z, A3.y*E3.z)));
  p2.z = fmaf(A0.z,E0.z, fmaf(A1.z,E1.z, fmaf(A2.z,E2.z, A3.z*E3.z)));
  p2.w = fmaf(A0.w,E0.z, fmaf(A1.w,E1.z, fmaf(A2.w,E2.z, A3.w*E3.z)));

  // reduce over cg (lanes differing in bits 1..4)
#pragma unroll
  for (int m = 2; m <= 16; m <<= 1) {
    p0.x += __shfl_xor_sync(0xffffffffu, p0.x, m);
    p0.y += __shfl_xor_sync(0xffffffffu, p0.y, m);
    p0.z += __shfl_xor_sync(0xffffffffu, p0.z, m);
    p0.w += __shfl_xor_sync(0xffffffffu, p0.w, m);
    p1.x += __shfl_xor_sync(0xffffffffu, p1.x, m);
    p1.y += __shfl_xor_sync(0xffffffffu, p1.y, m);
    p1.z += __shfl_xor_sync(0xffffffffu, p1.z, m);
    p1.w += __shfl_xor_sync(0xffffffffu, p1.w, m);
    p2.x += __shfl_xor_sync(0xffffffffu, p2.x, m);
    p2.y += __shfl_xor_sync(0xffffffffu, p2.y, m);
    p2.z += __shfl_xor_sync(0xffffffffu, p2.z, m);
    p2.w += __shfl_xor_sync(0xffffffffu, p2.w, m);
  }
  if (cg == 0) {                      // lanes 0 (nodes 0-3) and 1 (nodes 4-7)
    float* d = scp + SLATP + ng*12;
    d[0]  = p0.x; d[1]  = p1.x; d[2]  = p2.x;
    d[3]  = p0.y; d[4]  = p1.y; d[5]  = p2.y;
    d[6]  = p0.z; d[7]  = p1.z; d[8]  = p2.z;
    d[9]  = p0.w; d[10] = p1.w; d[11] = p2.w;
  }
  __syncwarp();
}

__global__ __launch_bounds__(THREADS, 1)
void gae7_kernel(KParams kp, float* __restrict__ out)
{
  float* ws = smem;
  const int tid = threadIdx.x;

  // ================= stage weights =================
  cpy(ws+EW1, kp.w[0], 192, tid); cpy(ws+EB1, kp.w[1], 64, tid);
  cpy(ws+EW2P, kp.w[2], 4096, tid);
  cpy(ws+EB2P, kp.w[3], 64, tid);
  { const float* w4 = kp.w[4];
    for (int i = tid; i < 256; i += THREADS) {
      int c = i >> 2, l = i & 3;
      ws[EW3P + i] = (l < 3) ? w4[c*3 + l] : 0.f;
    } }
  if (tid < 4) ws[EB3+tid] = (tid < 3) ? kp.w[5][tid] : 0.f;
  cpy(ws+G1WL, kp.w[6], 192, tid);  cpy(ws+G1BL, kp.w[7], 64, tid);
  cpy(ws+G1WR, kp.w[8], 192, tid);  cpy(ws+G1BR, kp.w[9], 64, tid);
  cpy(ws+G1WE, kp.w[10], 64, tid);  cpy(ws+G1ATT, kp.w[11], 64, tid);
  cpy(ws+G1BIAS, kp.w[12], 64, tid);
  { const float* wl = kp.w[13]; const float* wr = kp.w[15];
    for (int i = tid; i < 192; i += THREADS) {
      int k = i / 3, l = i - k*3;
      ws[G2WLT + l*64 + k] = wl[i];
      ws[G2WRT + l*64 + k] = wr[i];
    } }
  if (tid < 4) {
    ws[G2BL4 + tid]   = (tid < 3) ? kp.w[14][tid] : 0.f;
    ws[G2BR4 + tid]   = (tid < 3) ? kp.w[16][tid] : 0.f;
    ws[G2WE4 + tid]   = (tid < 3) ? kp.w[17][tid] : 0.f;
    ws[G2ATT4 + tid]  = (tid < 3) ? kp.w[18][tid] : 0.f;
    ws[G2BIAS4 + tid] = (tid < 3) ? kp.w[19][tid] : 0.f;
  }
  if (tid < 12) ws[SKW+tid] = (tid < 9) ? kp.w[20][tid] : 0.f;
  if (tid < 4)  ws[SKB+tid] = (tid < 3) ? kp.w[21][tid] : 0.f;
  cpy(ws+DW1, kp.w[22], 192, tid); cpy(ws+DB1, kp.w[23], 64, tid);
  cpy(ws+DW2P, kp.w[24], 4096, tid);
  cpy(ws+DB2P, kp.w[25], 64, tid);
  { const float* w26 = kp.w[26];
    for (int i = tid; i < 256; i += THREADS) {
      int c = i >> 2, l = i & 3;
      ws[DW3P + i] = (l < 3) ? w26[c*3 + l] : 0.f;
    } }
  if (tid < 4) ws[DB3+tid] = (tid < 3) ? kp.w[27][tid] : 0.f;

  const int g = tid >> 5;
  const int t = tid & 31;
  float* sc = smem + WTOT + g*SPER;
  const int Btot = kp.B;
  const int s = blockIdx.x*SPB + g;
  const bool valid = (s < Btot);
  const int sl = valid ? s : (Btot - 1);

  if (t < 8) sc[SX + t] = kp.x[sl*8 + t];
  __syncthreads();

  const int n3 = t / 3, l3 = t - n3*3;    // (node, dim) map for t<24 phases

  // ================= encoder L1 (3->64), layout [c][n] stride 8 =================
  {
    float wn1 = ws[EW1+64+t],    wx1 = ws[EW1+128+t],    bb1 = ws[EB1+t];
    float wn2 = ws[EW1+64+t+32], wx2 = ws[EW1+128+t+32], bb2 = ws[EB1+t+32];
    float va[8], vb[8];
#pragma unroll
    for (int n = 0; n < 8; n++) {
      float xn = sc[SX + n];
      va[n] = fmaxf(fmaf(xn, wx1, fmaf((float)n, wn1, bb1)), 0.f);
      vb[n] = fmaxf(fmaf(xn, wx2, fmaf((float)n, wn2, bb2)), 0.f);
    }
    *(float4*)&sc[SA + t*8]          = make_float4(va[0],va[1],va[2],va[3]);
    *(float4*)&sc[SA + t*8 + 4]      = make_float4(va[4],va[5],va[6],va[7]);
    *(float4*)&sc[SA + (t+32)*8]     = make_float4(vb[0],vb[1],vb[2],vb[3]);
    *(float4*)&sc[SA + (t+32)*8 + 4] = make_float4(vb[4],vb[5],vb[6],vb[7]);
  }
  __syncwarp();

  // ================= encoder L2 (64x64, solo) + fused L3 =================
  mlp64_solo(sc + SA, sc, ws + EW2P, ws + EB2P, ws + EW3P, t);

  if (t < 24)
    sc[SLAT + n3*4 + l3] = sc[SLATP + t] + ws[EB3 + l3];
  __syncwarp();

  // ================= normalize -> vis  (lane = l*8+n) =================
  {
    int ln_l = t >> 3, ln_n = t & 7;
    float v = sc[SLAT + ln_n*4 + ((ln_l < 3) ? ln_l : 0)];
    float sm = v;
    sm += __shfl_xor_sync(0xffffffffu, sm, 1);
    sm += __shfl_xor_sync(0xffffffffu, sm, 2);
    sm += __shfl_xor_sync(0xffffffffu, sm, 4);
    float c = v - sm*0.125f;
    float vv = c*c;
    vv += __shfl_xor_sync(0xffffffffu, vv, 1);
    vv += __shfl_xor_sync(0xffffffffu, vv, 2);
    vv += __shfl_xor_sync(0xffffffffu, vv, 4);
    float inv = 1.f / (sqrtf(vv * (1.f/7.f)) + 1e-8f);
    float visv = c*inv;
    if (t < 24) {
      sc[SVIS + ln_n*4 + ln_l] = visv;
      if (valid) {
        out[2*Btot*24 + s*24 + ln_n*3 + ln_l] = visv;    // vis
        float xpv = (l3 == 0) ? 0.f : ((l3 == 1) ? (float)n3 : sc[SX + n3]);
        out[s*24 + t] = xpv;                             // xp
      }
    }
  }
  __syncwarp();

  // ================= Gabriel graph (2 pairs per lane: p=t, p=t+32) =================
  {
    float4 Pv[8];
#pragma unroll
    for (int n = 0; n < 8; n++) Pv[n] = *(const float4*)&sc[SVIS + n*4];
    int i0 = t >> 3, j0 = t & 7;
    int i1 = (t + 32) >> 3;
    float4 pi0 = Pv[i0], pj0 = Pv[j0], pi1 = Pv[i1];
    float a0, d0, a1, d1;
    {
      float mx=(pi0.x+pj0.x)*0.5f, my=(pi0.y+pj0.y)*0.5f, mz=(pi0.z+pj0.z)*0.5f;
      float rx=pi0.x-mx, ry=pi0.y-my, rz=pi0.z-mz;
      float r2 = rx*rx+ry*ry+rz*rz;
      bool viol = false;
#pragma unroll
      for (int k = 0; k < 8; k++) {
        float ex=Pv[k].x-mx, ey=Pv[k].y-my, ez=Pv[k].z-mz;
        float d2 = ex*ex+ey*ey+ez*ez;
        viol |= (k != i0) && (k != j0) && (d2 < r2);
      }
      a0 = (!viol && (i0 != j0)) ? 1.f : 0.f;
      float dx=pi0.x-pj0.x, dy=pi0.y-pj0.y, dz=pi0.z-pj0.z;
      d0 = sqrtf(dx*dx+dy*dy+dz*dz + 1e-30f);
    }
    {
      float mx=(pi1.x+pj0.x)*0.5f, my=(pi1.y+pj0.y)*0.5f, mz=(pi1.z+pj0.z)*0.5f;
      float rx=pi1.x-mx, ry=pi1.y-my, rz=pi1.z-mz;
      float r2 = rx*rx+ry*ry+rz*rz;
      bool viol = false;
#pragma unroll
      for (int k = 0; k < 8; k++) {
        float ex=Pv[k].x-mx, ey=Pv[k].y-my, ez=Pv[k].z-mz;
        float d2 = ex*ex+ey*ey+ez*ez;
        viol |= (k != i1) && (k != j0) && (d2 < r2);
      }
      a1 = (!viol && (i1 != j0)) ? 1.f : 0.f;
      float dx=pi1.x-pj0.x, dy=pi1.y-pj0.y, dz=pi1.z-pj0.z;
      d1 = sqrtf(dx*dx+dy*dy+dz*dz + 1e-30f);
    }
    float as = a0 + a1, ds = a0*d0 + a1*d1;
#pragma unroll
    for (int m = 16; m; m >>= 1) {
      as += __shfl_xor_sync(0xffffffffu, as, m);
      ds += __shfl_xor_sync(0xffffffffu, ds, m);
    }
    float ma = ds / fmaxf(as, 1.f);
    sc[SEAT + t]      = (i0 == j0) ? ma  : d0;
    sc[SEAT + t + 32] = (i1 == j0) ? ma  : d1;
    sc[SMSK + t]      = (i0 == j0) ? 1.f : a0;
    sc[SMSK + t + 32] = (i1 == j0) ? 1.f : a1;
    if (valid) {
      out[3*Btot*24 + s*64 + t]      = a0;
      out[3*Btot*24 + s*64 + t + 32] = a1;
    }
  }

  // ================= GAT1 linear (3->64 xl, xr)  [n][c] stride 68 =================
  {
    float wl0a=ws[G1WL+t],    wl1a=ws[G1WL+64+t],    wl2a=ws[G1WL+128+t],    bla=ws[G1BL+t];
    float wl0b=ws[G1WL+t+32], wl1b=ws[G1WL+64+t+32], wl2b=ws[G1WL+128+t+32], blb=ws[G1BL+t+32];
    float wr0a=ws[G1WR+t],    wr1a=ws[G1WR+64+t],    wr2a=ws[G1WR+128+t],    bra=ws[G1BR+t];
    float wr0b=ws[G1WR+t+32], wr1b=ws[G1WR+64+t+32], wr2b=ws[G1WR+128+t+32], brb=ws[G1BR+t+32];
#pragma unroll
    for (int n = 0; n < 8; n++) {
      float4 la = *(const float4*)&sc[SLAT + n*4];
      sc[SXL + n*68 + t]      = fmaf(la.x, wl0a, fmaf(la.y, wl1a, fmaf(la.z, wl2a, bla)));
      sc[SXL + n*68 + t + 32] = fmaf(la.x, wl0b, fmaf(la.y, wl1b, fmaf(la.z, wl2b, blb)));
      sc[SXR + n*68 + t]      = fmaf(la.x, wr0a, fmaf(la.y, wr1a, fmaf(la.z, wr2a, bra)));
      sc[SXR + n*68 + t + 32] = fmaf(la.x, wr0b, fmaf(la.y, wr1b, fmaf(la.z, wr2b, brb)));
    }
  }
  __syncwarp();

  // ================= GAT1 edge scores + softmax (pairs 2t, 2t+1) =================
  {
    const int i = t >> 2;
    const int jj = (t & 3) * 2;
    const float* xr = sc + SXR + i*68;
    const float* xa = sc + SXL + jj*68;
    float2 ea = *(const float2*)&sc[SEAT + 2*t];
    float2 mk = *(const float2*)&sc[SMSK + 2*t];
    float acc0 = 0.f, acc1 = 0.f;
#pragma unroll 8
    for (int c = 0; c < 64; c += 4) {
      float4 r  = *(const float4*)&xr[c];
      float4 l0 = *(const float4*)&xa[c];
      float4 l1 = *(const float4*)&xa[c + 68];
      float4 we = *(const float4*)&ws[G1WE + c];
      float4 at = *(const float4*)&ws[G1ATT + c];
      acc0 = fmaf(lrelu(fmaf(ea.x, we.x, r.x) + l0.x), at.x, acc0);
      acc1 = fmaf(lrelu(fmaf(ea.y, we.x, r.x) + l1.x), at.x, acc1);
      acc0 = fmaf(lrelu(fmaf(ea.x, we.y, r.y) + l0.y), at.y, acc0);
      acc1 = fmaf(lrelu(fmaf(ea.y, we.y, r.y) + l1.y), at.y, acc1);
      acc0 = fmaf(lrelu(fmaf(ea.x, we.z, r.z) + l0.z), at.z, acc0);
      acc1 = fmaf(lrelu(fmaf(ea.y, we.z, r.z) + l1.z), at.z, acc1);
      acc0 = fmaf(lrelu(fmaf(ea.x, we.w, r.w) + l0.w), at.w, acc0);
      acc1 = fmaf(lrelu(fmaf(ea.y, we.w, r.w) + l1.w), at.w, acc1);
    }
    float e0 = (mk.x != 0.f) ? acc0 : -1e30f;
    float e1 = (mk.y != 0.f) ? acc1 : -1e30f;
    float m = fmaxf(e0, e1);
    m = fmaxf(m, __shfl_xor_sync(0xffffffffu, m, 1));
    m = fmaxf(m, __shfl_xor_sync(0xffffffffu, m, 2));
    float x0 = __expf(e0 - m), x1 = __expf(e1 - m);
    float sden = x0 + x1;
    sden += __shfl_xor_sync(0xffffffffu, sden, 1);
    sden += __shfl_xor_sync(0xffffffffu, sden, 2);
    float inv = 1.f / sden;
    *(float2*)&sc[SALPHA + 2*t] = make_float2(x0*inv*mk.x, x1*inv*mk.y);
  }
  __syncwarp();

  // ================= GAT1 aggregation -> h1 (into SXR), relu =================
  {
    float acc1[8], acc2[8];
    float b1 = ws[G1BIAS + t], b2 = ws[G1BIAS + t + 32];
#pragma unroll
    for (int i = 0; i < 8; i++) { acc1[i] = b1; acc2[i] = b2; }
#pragma unroll
    for (int j = 0; j < 8; j += 2) {
      float xv1a = sc[SXL + j*68 + t],       xv2a = sc[SXL + j*68 + t + 32];
      float xv1b = sc[SXL + (j+1)*68 + t],   xv2b = sc[SXL + (j+1)*68 + t + 32];
#pragma unroll
      for (int i = 0; i < 8; i++) {
        float2 al = *(const float2*)&sc[SALPHA + i*8 + j];
        acc1[i] = fmaf(al.x, xv1a, fmaf(al.y, xv1b, acc1[i]));
        acc2[i] = fmaf(al.x, xv2a, fmaf(al.y, xv2b, acc2[i]));
      }
    }
    __syncwarp();
#pragma unroll
    for (int i = 0; i < 8; i++) {
      sc[SXR + i*68 + t]      = fmaxf(acc1[i], 0.f);
      sc[SXR + i*68 + t + 32] = fmaxf(acc2[i], 0.f);
    }
  }
  __syncwarp();

  // ================= GAT2 linear (64->3 xl2, xr2) =================
  if (t < 24) {
    float a1 = ws[G2BL4 + l3], a2 = ws[G2BR4 + l3];
    const float* h1p = sc + SXR + n3*68;
#pragma unroll
    for (int c = 0; c < 64; c += 4) {
      float4 hh = *(const float4*)&h1p[c];
      float4 wl = *(const float4*)&ws[G2WLT + l3*64 + c];
      float4 wr = *(const float4*)&ws[G2WRT + l3*64 + c];
      a1 = fmaf(hh.x, wl.x, fmaf(hh.y, wl.y, fmaf(hh.z, wl.z, fmaf(hh.w, wl.w, a1))));
      a2 = fmaf(hh.x, wr.x, fmaf(hh.y, wr.y, fmaf(hh.z, wr.z, fmaf(hh.w, wr.w, a2))));
    }
    sc[SXL2 + n3*4 + l3] = a1;
    sc[SXR2 + n3*4 + l3] = a2;
  }
  __syncwarp();

  // ================= GAT2 edge scores + softmax =================
  {
    const int i = t >> 2;
    const int jj = (t & 3) * 2;
    float4 r   = *(const float4*)&sc[SXR2 + i*4];
    float4 l0  = *(const float4*)&sc[SXL2 + jj*4];
    float4 l1  = *(const float4*)&sc[SXL2 + (jj+1)*4];
    float4 we  = *(const float4*)&ws[G2WE4];
    float4 at  = *(const float4*)&ws[G2ATT4];
    float2 ea = *(const float2*)&sc[SEAT + 2*t];
    float2 mk = *(const float2*)&sc[SMSK + 2*t];
    float acc0 = 0.f, acc1 = 0.f;
    acc0 = fmaf(lrelu(fmaf(ea.x, we.x, r.x) + l0.x), at.x, acc0);
    acc1 = fmaf(lrelu(fmaf(ea.y, we.x, r.x) + l1.x), at.x, acc1);
    acc0 = fmaf(lrelu(fmaf(ea.x, we.y, r.y) + l0.y), at.y, acc0);
    acc1 = fmaf(lrelu(fmaf(ea.y, we.y, r.y) + l1.y), at.y, acc1);
    acc0 = fmaf(lrelu(fmaf(ea.x, we.z, r.z) + l0.z), at.z, acc0);
    acc1 = fmaf(lrelu(fmaf(ea.y, we.z, r.z) + l1.z), at.z, acc1);
    float e0 = (mk.x != 0.f) ? acc0 : -1e30f;
    float e1 = (mk.y != 0.f) ? acc1 : -1e30f;
    float m = fmaxf(e0, e1);
    m = fmaxf(m, __shfl_xor_sync(0xffffffffu, m, 1));
    m = fmaxf(m, __shfl_xor_sync(0xffffffffu, m, 2));
    float x0 = __expf(e0 - m), x1 = __expf(e1 - m);
    float sden = x0 + x1;
    sden += __shfl_xor_sync(0xffffffffu, sden, 1);
    sden += __shfl_xor_sync(0xffffffffu, sden, 2);
    float inv = 1.f / sden;
    *(float2*)&sc[SALPHA + 2*t] = make_float2(x0*inv*mk.x, x1*inv*mk.y);
  }
  __syncwarp();

  // ================= GAT2 aggregation + skip -> combined =================
  if (t < 24) {
    float acc = ws[G2BIAS4 + l3];
#pragma unroll
    for (int j = 0; j < 8; j++)
      acc = fmaf(sc[SALPHA + n3*8 + j], sc[SXL2 + j*4 + l3], acc);
    float4 la = *(const float4*)&sc[SLAT + n3*4];
    acc += fmaf(la.x, ws[SKW + l3],
           fmaf(la.y, ws[SKW + 3 + l3],
           fmaf(la.z, ws[SKW + 6 + l3], ws[SKB + l3])));
    sc[SCOMB + n3*4 + l3] = acc;
  }
  __syncwarp();

  // ================= decoder L1 (3->64) =================
  {
    float w0a=ws[DW1+t],    w1a=ws[DW1+64+t],    w2a=ws[DW1+128+t],    ba=ws[DB1+t];
    float w0b=ws[DW1+t+32], w1b=ws[DW1+64+t+32], w2b=ws[DW1+128+t+32], bb=ws[DB1+t+32];
    float va[8], vb[8];
#pragma unroll
    for (int n = 0; n < 8; n++) {
      float4 cm = *(const float4*)&sc[SCOMB + n*4];
      va[n] = fmaxf(fmaf(cm.x, w0a, fmaf(cm.y, w1a, fmaf(cm.z, w2a, ba))), 0.f);
      vb[n] = fmaxf(fmaf(cm.x, w0b, fmaf(cm.y, w1b, fmaf(cm.z, w2b, bb))), 0.f);
    }
    *(float4*)&sc[SA + t*8]          = make_float4(va[0],va[1],va[2],va[3]);
    *(float4*)&sc[SA + t*8 + 4]      = make_float4(va[4],va[5],va[6],va[7]);
    *(float4*)&sc[SA + (t+32)*8]     = make_float4(vb[0],vb[1],vb[2],vb[3]);
    *(float4*)&sc[SA + (t+32)*8 + 4] = make_float4(vb[4],vb[5],vb[6],vb[7]);
  }
  __syncwarp();

  // ================= decoder L2 (64x64, solo) + fused DW3 =================
  mlp64_solo(sc + SA, sc, ws + DW2P, ws + DB2P, ws + DW3P, t);

  if (valid && t < 24)
    out[Btot*24 + s*24 + t] = sc[SLATP + t] + ws[DB3 + l3];
}

extern "C" void kernel_launch(void* const* d_in, const int* in_sizes, int n_in,
                              void* d_out, int out_size)
{
  (void)n_in; (void)out_size;
  KParams kp;
  kp.x = (const float*)d_in[0];
  for (int i = 0; i < 28; i++) kp.w[i] = (const float*)d_in[i + 1];
  kp.B = in_sizes[0] / 8;

  cudaFuncSetAttribute(gae7_kernel, cudaFuncAttributeMaxDynamicSharedMemorySize, SMEM_BYTES);
  int grid = (kp.B + SPB - 1) / SPB;
  gae7_kernel<<<grid, THREADS, SMEM_BYTES>>>(kp, (float*)d_out);
}

// round 8
// speedup vs baseline: 1.1746x; 1.0363x over previous
#include <cuda_runtime.h>

#define SPB 32           // samples per block (1 solo warp per sample)
#define THREADS 1024     // one block per SM; single shared weight copy

// ---- weight offsets in shared (floats) ----
enum {
  EW1=0, EB1=192, EW2P=256, EB2P=4352, EW3P=4416, EB3=4672,
  G1WL=4676, G1BL=4868, G1WR=4932, G1BR=5124, G1WE=5188, G1ATT=5252, G1BIAS=5316,
  G2WLT=5380, G2BL4=5572, G2WRT=5576, G2BR4=5768,
  G2WE4=5772, G2ATT4=5776, G2BIAS4=5780,
  SKW=5784, SKB=5796,
  DW1=5800, DB1=5992, DW2P=6056, DB2P=10152, DW3P=10216, DB3=10472,
  WTOT=10476
};
// ---- per-sample scratch offsets (floats) ----
enum {
  SA=0, SLATP=512, SXL=0, SXR=544,
  SEAT=1088, SMSK=1152, SALPHA=1216,
  SLAT=1280, SVIS=1312, SCOMB=1344, SXL2=1376, SXR2=1408, SX=1440,
  SPER=1456
};

#define SMEM_FLOATS (WTOT + SPB*SPER)
#define SMEM_BYTES  (SMEM_FLOATS*4)   // 228,272 bytes -> 1 block/SM, 32 warps

struct KParams {
  const float* x;
  const float* w[28];
  int B;
};

extern __shared__ float smem[];

__device__ __forceinline__ void cpy(float* dst, const float* src, int n, int tid) {
  for (int i = tid; i < n; i += THREADS) dst[i] = src[i];
}

__device__ __forceinline__ float lrelu(float h) {
  return fmaxf(h, 0.2f*h);          // 2 ops: FMUL + FMNMX
}

__device__ __forceinline__ unsigned sm_u32(const void* p) {
  unsigned a;
  asm("{ .reg .u64 t; cvta.to.shared.u64 t, %1; cvt.u32.u64 %0, t; }"
      : "=r"(a) : "l"(p));
  return a;
}

// Solo-warp 8x64 @ 64x64 + relu + fused (64->3) projection, f32x2 mainloop.
// Lane: ng = t&1 (nodes 4ng..4ng+3), cg = t>>1 (channels 4cg..4cg+3).
// Accumulators packed over channel pairs: A01[n] = {acc(4cg+0,n), acc(4cg+1,n)}.
// in: [k][8 nodes] stride 8 floats. Wp: [k][64]. Leaves latent partials in
// scp[SLATP + n*3 + l]; caller adds bias after __syncwarp.
__device__ __forceinline__ void mlp64_solo(
    const float* __restrict__ in, float* scp,
    const float* __restrict__ Wp, const float* __restrict__ bp,
    const float* __restrict__ W3p, int t)
{
  const int ng = t & 1, cg = t >> 1;
  const unsigned abase = sm_u32(in) + ng*16u;
  const unsigned wbase = sm_u32(Wp) + cg*16u;

  float4 b4 = *(const float4*)&bp[cg*4];
  unsigned long long A01[4], A23[4];
  {
    unsigned long long b01, b23;
    asm("mov.b64 %0, {%1,%2};" : "=l"(b01) : "f"(b4.x), "f"(b4.y));
    asm("mov.b64 %0, {%1,%2};" : "=l"(b23) : "f"(b4.z), "f"(b4.w));
#pragma unroll
    for (int n = 0; n < 4; n++) { A01[n] = b01; A23[n] = b23; }
  }

#pragma unroll 8
  for (int k = 0; k < 64; k++) {
    unsigned aa = abase + (unsigned)(k*32);
    unsigned wa = wbase + (unsigned)(k*256);
    unsigned long long ar01, ar23, w01, w23;
    asm("ld.shared.v2.u64 {%0,%1}, [%2];" : "=l"(ar01), "=l"(ar23) : "r"(aa));
    asm("ld.shared.v2.u64 {%0,%1}, [%2];" : "=l"(w01),  "=l"(w23)  : "r"(wa));
    float a0, a1, a2, a3;
    asm("mov.b64 {%0,%1}, %2;" : "=f"(a0), "=f"(a1) : "l"(ar01));
    asm("mov.b64 {%0,%1}, %2;" : "=f"(a2), "=f"(a3) : "l"(ar23));
    unsigned long long a0d, a1d, a2d, a3d;
    asm("mov.b64 %0, {%1,%1};" : "=l"(a0d) : "f"(a0));
    asm("mov.b64 %0, {%1,%1};" : "=l"(a1d) : "f"(a1));
    asm("mov.b64 %0, {%1,%1};" : "=l"(a2d) : "f"(a2));
    asm("mov.b64 %0, {%1,%1};" : "=l"(a3d) : "f"(a3));
    asm("fma.rn.f32x2 %0, %1, %2, %0;" : "+l"(A01[0]) : "l"(w01), "l"(a0d));
    asm("fma.rn.f32x2 %0, %1, %2, %0;" : "+l"(A23[0]) : "l"(w23), "l"(a0d));
    asm("fma.rn.f32x2 %0, %1, %2, %0;" : "+l"(A01[1]) : "l"(w01), "l"(a1d));
    asm("fma.rn.f32x2 %0, %1, %2, %0;" : "+l"(A23[1]) : "l"(w23), "l"(a1d));
    asm("fma.rn.f32x2 %0, %1, %2, %0;" : "+l"(A01[2]) : "l"(w01), "l"(a2d));
    asm("fma.rn.f32x2 %0, %1, %2, %0;" : "+l"(A23[2]) : "l"(w23), "l"(a2d));
    asm("fma.rn.f32x2 %0, %1, %2, %0;" : "+l"(A01[3]) : "l"(w01), "l"(a3d));
    asm("fma.rn.f32x2 %0, %1, %2, %0;" : "+l"(A23[3]) : "l"(w23), "l"(a3d));
  }

  // unpack accumulators: Ac[n] = activation of channel 4cg+c at node 4ng+n
  float A0[4], A1[4], A2[4], A3[4];
#pragma unroll
  for (int n = 0; n < 4; n++) {
    asm("mov.b64 {%0,%1}, %2;" : "=f"(A0[n]), "=f"(A1[n]) : "l"(A01[n]));
    asm("mov.b64 {%0,%1}, %2;" : "=f"(A2[n]), "=f"(A3[n]) : "l"(A23[n]));
  }
#pragma unroll
  for (int n = 0; n < 4; n++) {
    A0[n] = fmaxf(A0[n], 0.f); A1[n] = fmaxf(A1[n], 0.f);
    A2[n] = fmaxf(A2[n], 0.f); A3[n] = fmaxf(A3[n], 0.f);
  }

  const int p0i = cg*4;
  float4 E0 = *(const float4*)&W3p[(p0i+0)*4];
  float4 E1 = *(const float4*)&W3p[(p0i+1)*4];
  float4 E2 = *(const float4*)&W3p[(p0i+2)*4];
  float4 E3 = *(const float4*)&W3p[(p0i+3)*4];

  float p[3][4];
#pragma unroll
  for (int n = 0; n < 4; n++) {
    p[0][n] = fmaf(A0[n],E0.x, fmaf(A1[n],E1.x, fmaf(A2[n],E2.x, A3[n]*E3.x)));
    p[1][n] = fmaf(A0[n],E0.y, fmaf(A1[n],E1.y, fmaf(A2[n],E2.y, A3[n]*E3.y)));
    p[2][n] = fmaf(A0[n],E0.z, fmaf(A1[n],E1.z, fmaf(A2[n],E2.z, A3[n]*E3.z)));
  }

  // reduce over cg (lanes differing in bits 1..4)
#pragma unroll
  for (int m = 2; m <= 16; m <<= 1) {
#pragma unroll
    for (int l = 0; l < 3; l++)
#pragma unroll
      for (int n = 0; n < 4; n++)
        p[l][n] += __shfl_xor_sync(0xffffffffu, p[l][n], m);
  }
  if (cg == 0) {
    float* d = scp + SLATP + ng*12;
#pragma unroll
    for (int n = 0; n < 4; n++) {
      d[n*3 + 0] = p[0][n]; d[n*3 + 1] = p[1][n]; d[n*3 + 2] = p[2][n];
    }
  }
  __syncwarp();
}

__global__ __launch_bounds__(THREADS, 1)
void gae8_kernel(KParams kp, float* __restrict__ out)
{
  float* ws = smem;
  const int tid = threadIdx.x;

  // ================= stage weights =================
  cpy(ws+EW1, kp.w[0], 192, tid); cpy(ws+EB1, kp.w[1], 64, tid);
  cpy(ws+EW2P, kp.w[2], 4096, tid);
  cpy(ws+EB2P, kp.w[3], 64, tid);
  { const float* w4 = kp.w[4];
    for (int i = tid; i < 256; i += THREADS) {
      int c = i >> 2, l = i & 3;
      ws[EW3P + i] = (l < 3) ? w4[c*3 + l] : 0.f;
    } }
  if (tid < 4) ws[EB3+tid] = (tid < 3) ? kp.w[5][tid] : 0.f;
  cpy(ws+G1WL, kp.w[6], 192, tid);  cpy(ws+G1BL, kp.w[7], 64, tid);
  cpy(ws+G1WR, kp.w[8], 192, tid);  cpy(ws+G1BR, kp.w[9], 64, tid);
  cpy(ws+G1WE, kp.w[10], 64, tid);  cpy(ws+G1ATT, kp.w[11], 64, tid);
  cpy(ws+G1BIAS, kp.w[12], 64, tid);
  { const float* wl = kp.w[13]; const float* wr = kp.w[15];
    for (int i = tid; i < 192; i += THREADS) {
      int k = i / 3, l = i - k*3;
      ws[G2WLT + l*64 + k] = wl[i];
      ws[G2WRT + l*64 + k] = wr[i];
    } }
  if (tid < 4) {
    ws[G2BL4 + tid]   = (tid < 3) ? kp.w[14][tid] : 0.f;
    ws[G2BR4 + tid]   = (tid < 3) ? kp.w[16][tid] : 0.f;
    ws[G2WE4 + tid]   = (tid < 3) ? kp.w[17][tid] : 0.f;
    ws[G2ATT4 + tid]  = (tid < 3) ? kp.w[18][tid] : 0.f;
    ws[G2BIAS4 + tid] = (tid < 3) ? kp.w[19][tid] : 0.f;
  }
  if (tid < 12) ws[SKW+tid] = (tid < 9) ? kp.w[20][tid] : 0.f;
  if (tid < 4)  ws[SKB+tid] = (tid < 3) ? kp.w[21][tid] : 0.f;
  cpy(ws+DW1, kp.w[22], 192, tid); cpy(ws+DB1, kp.w[23], 64, tid);
  cpy(ws+DW2P, kp.w[24], 4096, tid);
  cpy(ws+DB2P, kp.w[25], 64, tid);
  { const float* w26 = kp.w[26];
    for (int i = tid; i < 256; i += THREADS) {
      int c = i >> 2, l = i & 3;
      ws[DW3P + i] = (l < 3) ? w26[c*3 + l] : 0.f;
    } }
  if (tid < 4) ws[DB3+tid] = (tid < 3) ? kp.w[27][tid] : 0.f;

  const int g = tid >> 5;
  const int t = tid & 31;
  float* sc = smem + WTOT + g*SPER;
  const int Btot = kp.B;
  const int s = blockIdx.x*SPB + g;
  const bool valid = (s < Btot);
  const int sl = valid ? s : (Btot - 1);

  if (t < 8) sc[SX + t] = kp.x[sl*8 + t];
  __syncthreads();

  const int n3 = t / 3, l3 = t - n3*3;    // (node, dim) map for t<24 phases

  // ================= encoder L1 (3->64), layout [c][n] stride 8 =================
  {
    float wn1 = ws[EW1+64+t],    wx1 = ws[EW1+128+t],    bb1 = ws[EB1+t];
    float wn2 = ws[EW1+64+t+32], wx2 = ws[EW1+128+t+32], bb2 = ws[EB1+t+32];
    float va[8], vb[8];
#pragma unroll
    for (int n = 0; n < 8; n++) {
      float xn = sc[SX + n];
      va[n] = fmaxf(fmaf(xn, wx1, fmaf((float)n, wn1, bb1)), 0.f);
      vb[n] = fmaxf(fmaf(xn, wx2, fmaf((float)n, wn2, bb2)), 0.f);
    }
    *(float4*)&sc[SA + t*8]          = make_float4(va[0],va[1],va[2],va[3]);
    *(float4*)&sc[SA + t*8 + 4]      = make_float4(va[4],va[5],va[6],va[7]);
    *(float4*)&sc[SA + (t+32)*8]     = make_float4(vb[0],vb[1],vb[2],vb[3]);
    *(float4*)&sc[SA + (t+32)*8 + 4] = make_float4(vb[4],vb[5],vb[6],vb[7]);
  }
  __syncwarp();

  // ================= encoder L2 (64x64, f32x2) + fused L3 =================
  mlp64_solo(sc + SA, sc, ws + EW2P, ws + EB2P, ws + EW3P, t);

  if (t < 24)
    sc[SLAT + n3*4 + l3] = sc[SLATP + t] + ws[EB3 + l3];
  __syncwarp();

  // ================= normalize -> vis  (lane = l*8+n) =================
  {
    int ln_l = t >> 3, ln_n = t & 7;
    float v = sc[SLAT + ln_n*4 + ((ln_l < 3) ? ln_l : 0)];
    float sm = v;
    sm += __shfl_xor_sync(0xffffffffu, sm, 1);
    sm += __shfl_xor_sync(0xffffffffu, sm, 2);
    sm += __shfl_xor_sync(0xffffffffu, sm, 4);
    float c = v - sm*0.125f;
    float vv = c*c;
    vv += __shfl_xor_sync(0xffffffffu, vv, 1);
    vv += __shfl_xor_sync(0xffffffffu, vv, 2);
    vv += __shfl_xor_sync(0xffffffffu, vv, 4);
    float inv = 1.f / (sqrtf(vv * (1.f/7.f)) + 1e-8f);
    float visv = c*inv;
    if (t < 24) {
      sc[SVIS + ln_n*4 + ln_l] = visv;
      if (valid) {
        out[2*Btot*24 + s*24 + ln_n*3 + ln_l] = visv;    // vis
        float xpv = (l3 == 0) ? 0.f : ((l3 == 1) ? (float)n3 : sc[SX + n3]);
        out[s*24 + t] = xpv;                             // xp
      }
    }
  }
  __syncwarp();

  // ================= Gabriel graph (2 pairs per lane: p=t, p=t+32) =================
  {
    float4 Pv[8];
#pragma unroll
    for (int n = 0; n < 8; n++) Pv[n] = *(const float4*)&sc[SVIS + n*4];
    int i0 = t >> 3, j0 = t & 7;
    int i1 = (t + 32) >> 3;
    float4 pi0 = Pv[i0], pj0 = Pv[j0], pi1 = Pv[i1];
    float a0, d0, a1, d1;
    {
      float mx=(pi0.x+pj0.x)*0.5f, my=(pi0.y+pj0.y)*0.5f, mz=(pi0.z+pj0.z)*0.5f;
      float rx=pi0.x-mx, ry=pi0.y-my, rz=pi0.z-mz;
      float r2 = rx*rx+ry*ry+rz*rz;
      bool viol = false;
#pragma unroll
      for (int k = 0; k < 8; k++) {
        float ex=Pv[k].x-mx, ey=Pv[k].y-my, ez=Pv[k].z-mz;
        float d2 = ex*ex+ey*ey+ez*ez;
        viol |= (k != i0) && (k != j0) && (d2 < r2);
      }
      a0 = (!viol && (i0 != j0)) ? 1.f : 0.f;
      float dx=pi0.x-pj0.x, dy=pi0.y-pj0.y, dz=pi0.z-pj0.z;
      d0 = sqrtf(dx*dx+dy*dy+dz*dz + 1e-30f);
    }
    {
      float mx=(pi1.x+pj0.x)*0.5f, my=(pi1.y+pj0.y)*0.5f, mz=(pi1.z+pj0.z)*0.5f;
      float rx=pi1.x-mx, ry=pi1.y-my, rz=pi1.z-mz;
      float r2 = rx*rx+ry*ry+rz*rz;
      bool viol = false;
#pragma unroll
      for (int k = 0; k < 8; k++) {
        float ex=Pv[k].x-mx, ey=Pv[k].y-my, ez=Pv[k].z-mz;
        float d2 = ex*ex+ey*ey+ez*ez;
        viol |= (k != i1) && (k != j0) && (d2 < r2);
      }
      a1 = (!viol && (i1 != j0)) ? 1.f : 0.f;
      float dx=pi1.x-pj0.x, dy=pi1.y-pj0.y, dz=pi1.z-pj0.z;
      d1 = sqrtf(dx*dx+dy*dy+dz*dz + 1e-30f);
    }
    float as = a0 + a1, ds = a0*d0 + a1*d1;
#pragma unroll
    for (int m = 16; m; m >>= 1) {
      as += __shfl_xor_sync(0xffffffffu, as, m);
      ds += __shfl_xor_sync(0xffffffffu, ds, m);
    }
    float ma = ds / fmaxf(as, 1.f);
    sc[SEAT + t]      = (i0 == j0) ? ma  : d0;
    sc[SEAT + t + 32] = (i1 == j0) ? ma  : d1;
    sc[SMSK + t]      = (i0 == j0) ? 1.f : a0;
    sc[SMSK + t + 32] = (i1 == j0) ? 1.f : a1;
    if (valid) {
      out[3*Btot*24 + s*64 + t]      = a0;
      out[3*Btot*24 + s*64 + t + 32] = a1;
    }
  }

  // ================= GAT1 linear (3->64 xl, xr)  [n][c] stride 68 =================
  {
    float wl0a=ws[G1WL+t],    wl1a=ws[G1WL+64+t],    wl2a=ws[G1WL+128+t],    bla=ws[G1BL+t];
    float wl0b=ws[G1WL+t+32], wl1b=ws[G1WL+64+t+32], wl2b=ws[G1WL+128+t+32], blb=ws[G1BL+t+32];
    float wr0a=ws[G1WR+t],    wr1a=ws[G1WR+64+t],    wr2a=ws[G1WR+128+t],    bra=ws[G1BR+t];
    float wr0b=ws[G1WR+t+32], wr1b=ws[G1WR+64+t+32], wr2b=ws[G1WR+128+t+32], brb=ws[G1BR+t+32];
#pragma unroll
    for (int n = 0; n < 8; n++) {
      float4 la = *(const float4*)&sc[SLAT + n*4];
      sc[SXL + n*68 + t]      = fmaf(la.x, wl0a, fmaf(la.y, wl1a, fmaf(la.z, wl2a, bla)));
      sc[SXL + n*68 + t + 32] = fmaf(la.x, wl0b, fmaf(la.y, wl1b, fmaf(la.z, wl2b, blb)));
      sc[SXR + n*68 + t]      = fmaf(la.x, wr0a, fmaf(la.y, wr1a, fmaf(la.z, wr2a, bra)));
      sc[SXR + n*68 + t + 32] = fmaf(la.x, wr0b, fmaf(la.y, wr1b, fmaf(la.z, wr2b, brb)));
    }
  }
  __syncwarp();

  // ================= GAT1 edge scores + softmax (pairs 2t, 2t+1) =================
  {
    const int i = t >> 2;
    const int jj = (t & 3) * 2;
    const float* xr = sc + SXR + i*68;
    const float* xa = sc + SXL + jj*68;
    float2 ea = *(const float2*)&sc[SEAT + 2*t];
    float2 mk = *(const float2*)&sc[SMSK + 2*t];
    float acc0 = 0.f, acc1 = 0.f;
#pragma unroll 8
    for (int c = 0; c < 64; c += 4) {
      float4 r  = *(const float4*)&xr[c];
      float4 l0 = *(const float4*)&xa[c];
      float4 l1 = *(const float4*)&xa[c + 68];
      float4 we = *(const float4*)&ws[G1WE + c];
      float4 at = *(const float4*)&ws[G1ATT + c];
      acc0 = fmaf(lrelu(fmaf(ea.x, we.x, r.x) + l0.x), at.x, acc0);
      acc1 = fmaf(lrelu(fmaf(ea.y, we.x, r.x) + l1.x), at.x, acc1);
      acc0 = fmaf(lrelu(fmaf(ea.x, we.y, r.y) + l0.y), at.y, acc0);
      acc1 = fmaf(lrelu(fmaf(ea.y, we.y, r.y) + l1.y), at.y, acc1);
      acc0 = fmaf(lrelu(fmaf(ea.x, we.z, r.z) + l0.z), at.z, acc0);
      acc1 = fmaf(lrelu(fmaf(ea.y, we.z, r.z) + l1.z), at.z, acc1);
      acc0 = fmaf(lrelu(fmaf(ea.x, we.w, r.w) + l0.w), at.w, acc0);
      acc1 = fmaf(lrelu(fmaf(ea.y, we.w, r.w) + l1.w), at.w, acc1);
    }
    float e0 = (mk.x != 0.f) ? acc0 : -1e30f;
    float e1 = (mk.y != 0.f) ? acc1 : -1e30f;
    float m = fmaxf(e0, e1);
    m = fmaxf(m, __shfl_xor_sync(0xffffffffu, m, 1));
    m = fmaxf(m, __shfl_xor_sync(0xffffffffu, m, 2));
    float x0 = __expf(e0 - m), x1 = __expf(e1 - m);
    float sden = x0 + x1;
    sden += __shfl_xor_sync(0xffffffffu, sden, 1);
    sden += __shfl_xor_sync(0xffffffffu, sden, 2);
    float inv = 1.f / sden;
    *(float2*)&sc[SALPHA + 2*t] = make_float2(x0*inv*mk.x, x1*inv*mk.y);
  }
  __syncwarp();

  // ================= GAT1 aggregation -> h1 (into SXR), relu =================
  {
    float acc1[8], acc2[8];
    float b1 = ws[G1BIAS + t], b2 = ws[G1BIAS + t + 32];
#pragma unroll
    for (int i = 0; i < 8; i++) { acc1[i] = b1; acc2[i] = b2; }
#pragma unroll
    for (int j = 0; j < 8; j += 2) {
      float xv1a = sc[SXL + j*68 + t],       xv2a = sc[SXL + j*68 + t + 32];
      float xv1b = sc[SXL + (j+1)*68 + t],   xv2b = sc[SXL + (j+1)*68 + t + 32];
#pragma unroll
      for (int i = 0; i < 8; i++) {
        float2 al = *(const float2*)&sc[SALPHA + i*8 + j];
        acc1[i] = fmaf(al.x, xv1a, fmaf(al.y, xv1b, acc1[i]));
        acc2[i] = fmaf(al.x, xv2a, fmaf(al.y, xv2b, acc2[i]));
      }
    }
    __syncwarp();
#pragma unroll
    for (int i = 0; i < 8; i++) {
      sc[SXR + i*68 + t]      = fmaxf(acc1[i], 0.f);
      sc[SXR + i*68 + t + 32] = fmaxf(acc2[i], 0.f);
    }
  }
  __syncwarp();

  // ================= GAT2 linear (64->3 xl2, xr2) =================
  if (t < 24) {
    float a1 = ws[G2BL4 + l3], a2 = ws[G2BR4 + l3];
    const float* h1p = sc + SXR + n3*68;
#pragma unroll
    for (int c = 0; c < 64; c += 4) {
      float4 hh = *(const float4*)&h1p[c];
      float4 wl = *(const float4*)&ws[G2WLT + l3*64 + c];
      float4 wr = *(const float4*)&ws[G2WRT + l3*64 + c];
      a1 = fmaf(hh.x, wl.x, fmaf(hh.y, wl.y, fmaf(hh.z, wl.z, fmaf(hh.w, wl.w, a1))));
      a2 = fmaf(hh.x, wr.x, fmaf(hh.y, wr.y, fmaf(hh.z, wr.z, fmaf(hh.w, wr.w, a2))));
    }
    sc[SXL2 + n3*4 + l3] = a1;
    sc[SXR2 + n3*4 + l3] = a2;
  }
  __syncwarp();

  // ================= GAT2 edge scores + softmax =================
  {
    const int i = t >> 2;
    const int jj = (t & 3) * 2;
    float4 r   = *(const float4*)&sc[SXR2 + i*4];
    float4 l0  = *(const float4*)&sc[SXL2 + jj*4];
    float4 l1  = *(const float4*)&sc[SXL2 + (jj+1)*4];
    float4 we  = *(const float4*)&ws[G2WE4];
    float4 at  = *(const float4*)&ws[G2ATT4];
    float2 ea = *(const float2*)&sc[SEAT + 2*t];
    float2 mk = *(const float2*)&sc[SMSK + 2*t];
    float acc0 = 0.f, acc1 = 0.f;
    acc0 = fmaf(lrelu(fmaf(ea.x, we.x, r.x) + l0.x), at.x, acc0);
    acc1 = fmaf(lrelu(fmaf(ea.y, we.x, r.x) + l1.x), at.x, acc1);
    acc0 = fmaf(lrelu(fmaf(ea.x, we.y, r.y) + l0.y), at.y, acc0);
    acc1 = fmaf(lrelu(fmaf(ea.y, we.y, r.y) + l1.y), at.y, acc1);
    acc0 = fmaf(lrelu(fmaf(ea.x, we.z, r.z) + l0.z), at.z, acc0);
    acc1 = fmaf(lrelu(fmaf(ea.y, we.z, r.z) + l1.z), at.z, acc1);
    float e0 = (mk.x != 0.f) ? acc0 : -1e30f;
    float e1 = (mk.y != 0.f) ? acc1 : -1e30f;
    float m = fmaxf(e0, e1);
    m = fmaxf(m, __shfl_xor_sync(0xffffffffu, m, 1));
    m = fmaxf(m, __shfl_xor_sync(0xffffffffu, m, 2));
    float x0 = __expf(e0 - m), x1 = __expf(e1 - m);
    float sden = x0 + x1;
    sden += __shfl_xor_sync(0xffffffffu, sden, 1);
    sden += __shfl_xor_sync(0xffffffffu, sden, 2);
    float inv = 1.f / sden;
    *(float2*)&sc[SALPHA + 2*t] = make_float2(x0*inv*mk.x, x1*inv*mk.y);
  }
  __syncwarp();

  // ================= GAT2 aggregation + skip -> combined =================
  if (t < 24) {
    float acc = ws[G2BIAS4 + l3];
#pragma unroll
    for (int j = 0; j < 8; j++)
      acc = fmaf(sc[SALPHA + n3*8 + j], sc[SXL2 + j*4 + l3], acc);
    float4 la = *(const float4*)&sc[SLAT + n3*4];
    acc += fmaf(la.x, ws[SKW + l3],
           fmaf(la.y, ws[SKW + 3 + l3],
           fmaf(la.z, ws[SKW + 6 + l3], ws[SKB + l3])));
    sc[SCOMB + n3*4 + l3] = acc;
  }
  __syncwarp();

  // ================= decoder L1 (3->64) =================
  {
    float w0a=ws[DW1+t],    w1a=ws[DW1+64+t],    w2a=ws[DW1+128+t],    ba=ws[DB1+t];
    float w0b=ws[DW1+t+32], w1b=ws[DW1+64+t+32], w2b=ws[DW1+128+t+32], bb=ws[DB1+t+32];
    float va[8], vb[8];
#pragma unroll
    for (int n = 0; n < 8; n++) {
      float4 cm = *(const float4*)&sc[SCOMB + n*4];
      va[n] = fmaxf(fmaf(cm.x, w0a, fmaf(cm.y, w1a, fmaf(cm.z, w2a, ba))), 0.f);
      vb[n] = fmaxf(fmaf(cm.x, w0b, fmaf(cm.y, w1b, fmaf(cm.z, w2b, bb))), 0.f);
    }
    *(float4*)&sc[SA + t*8]          = make_float4(va[0],va[1],va[2],va[3]);
    *(float4*)&sc[SA + t*8 + 4]      = make_float4(va[4],va[5],va[6],va[7]);
    *(float4*)&sc[SA + (t+32)*8]     = make_float4(vb[0],vb[1],vb[2],vb[3]);
    *(float4*)&sc[SA + (t+32)*8 + 4] = make_float4(vb[4],vb[5],vb[6],vb[7]);
  }
  __syncwarp();

  // ================= decoder L2 (64x64, f32x2) + fused DW3 =================
  mlp64_solo(sc + SA, sc, ws + DW2P, ws + DB2P, ws + DW3P, t);

  if (valid && t < 24)
    out[Btot*24 + s*24 + t] = sc[SLATP + t] + ws[DB3 + l3];
}

extern "C" void kernel_launch(void* const* d_in, const int* in_sizes, int n_in,
                              void* d_out, int out_size)
{
  (void)n_in; (void)out_size;
  KParams kp;
  kp.x = (const float*)d_in[0];
  for (int i = 0; i < 28; i++) kp.w[i] = (const float*)d_in[i + 1];
  kp.B = in_sizes[0] / 8;

  cudaFuncSetAttribute(gae8_kernel, cudaFuncAttributeMaxDynamicSharedMemorySize, SMEM_BYTES);
  int grid = (kp.B + SPB - 1) / SPB;
  gae8_kernel<<<grid, THREADS, SMEM_BYTES>>>(kp, (float*)d_out);
}

// round 9
// speedup vs baseline: 1.2878x; 1.0964x over previous
#include <cuda_runtime.h>

#define SPB 37           // samples per block: 18 warps x 2 + warp18 x 1
#define WARPS 19
#define THREADS (WARPS*32)   // 608; grid = ceil(B/37) = 443 -> 3 waves

// ---- weight offsets in shared (floats) ----
enum {
  EW1=0, EB1=192, EW2P=256, EB2P=4352, EW3P=4416, EB3=4672,
  G1WL=4676, G1BL=4868, G1WR=4932, G1BR=5124, G1WE=5188, G1ATT=5252, G1BIAS=5316,
  G2WLT=5380, G2BL4=5572, G2WRT=5576, G2BR4=5768,
  G2WE4=5772, G2ATT4=5776, G2BIAS4=5780,
  SKW=5784, SKB=5796,
  DW1=5800, DB1=5992, DW2P=6056, DB2P=10152, DW3P=10216, DB3=10472,
  WTOT=10476
};
// ---- per-sample scratch (floats); heavy lifetime overlays ----
// U [0,1084): SA=[0,512) + SLATP=[512,560) | SXL=[0,540) s68 | SXR=[544,1084) s68
//             SXL2=[0,32) SXR2=[32,64) (GAT2 phase, SXL dead)
// SEM  [1084,1148): merged eat/mask (masked-out => -1.0); SX aliases its head (dead by Gabriel)
// SALPHA [1148,1212); SLAT [1212,1244); SVIS=[1244,1276) (SCOMB overlays SVIS)
enum {
  SA=0, SLATP=512, SXL=0, SXR=544, SXL2=0, SXR2=32,
  SEM=1084, SX=1084, SALPHA=1148, SLAT=1212, SVIS=1244, SCOMB=1244,
  SPER=1276
};

#define SMEM_FLOATS (WTOT + SPB*SPER)
#define SMEM_BYTES  (SMEM_FLOATS*4)   // 230,752 B -> 1 block/SM

struct KParams {
  const float* x;
  const float* w[28];
  int B;
};

extern __shared__ float smem[];

__device__ __forceinline__ void cpy(float* dst, const float* src, int n, int tid) {
  for (int i = tid; i < n; i += THREADS) dst[i] = src[i];
}

__device__ __forceinline__ float lrelu(float h) { return fmaxf(h, 0.2f*h); }

__device__ __forceinline__ unsigned sm_u32(const void* p) {
  unsigned a;
  asm("{ .reg .u64 t; cvta.to.shared.u64 t, %1; cvt.u32.u64 %0, t; }"
      : "=r"(a) : "l"(p));
  return a;
}

// Dual-sample 8x64 @ 64x64 + relu + fused (64->3) projection, f32x2.
// Lane: u = t&1 (sample), cg = t>>1 (channels 4cg..4cg+3) over ALL 8 nodes.
// Weight LDS shared across both samples. Leaves latent partials in
// sc(u)[SLATP + n*3 + l]; warp18's u=1 stores suppressed via ok1.
__device__ __forceinline__ void mlp64_dual(
    const float* __restrict__ in0, const float* __restrict__ in1,
    float* sc0, float* sc1, bool ok1,
    const float* __restrict__ Wp, const float* __restrict__ bp,
    const float* __restrict__ W3p, int t)
{
  const int u = t & 1, cg = t >> 1;
  const unsigned abase = sm_u32(u ? in1 : in0);
  const unsigned wbase = sm_u32(Wp) + cg*16u;

  float4 b4 = *(const float4*)&bp[cg*4];
  unsigned long long A01[8], A23[8];
  {
    unsigned long long b01, b23;
    asm("mov.b64 %0, {%1,%2};" : "=l"(b01) : "f"(b4.x), "f"(b4.y));
    asm("mov.b64 %0, {%1,%2};" : "=l"(b23) : "f"(b4.z), "f"(b4.w));
#pragma unroll
    for (int n = 0; n < 8; n++) { A01[n] = b01; A23[n] = b23; }
  }

#pragma unroll 4
  for (int k = 0; k < 64; k++) {
    unsigned aa = abase + (unsigned)(k*32);
    unsigned wa = wbase + (unsigned)(k*256);
    unsigned long long ar0, ar1, ar2, ar3, w01, w23;
    asm("ld.shared.v2.u64 {%0,%1}, [%2];" : "=l"(ar0), "=l"(ar1) : "r"(aa));
    asm("ld.shared.v2.u64 {%0,%1}, [%2];" : "=l"(ar2), "=l"(ar3) : "r"(aa+16u));
    asm("ld.shared.v2.u64 {%0,%1}, [%2];" : "=l"(w01),  "=l"(w23)  : "r"(wa));
    float a[8];
    asm("mov.b64 {%0,%1}, %2;" : "=f"(a[0]), "=f"(a[1]) : "l"(ar0));
    asm("mov.b64 {%0,%1}, %2;" : "=f"(a[2]), "=f"(a[3]) : "l"(ar1));
    asm("mov.b64 {%0,%1}, %2;" : "=f"(a[4]), "=f"(a[5]) : "l"(ar2));
    asm("mov.b64 {%0,%1}, %2;" : "=f"(a[6]), "=f"(a[7]) : "l"(ar3));
#pragma unroll
    for (int n = 0; n < 8; n++) {
      unsigned long long dn;
      asm("mov.b64 %0, {%1,%1};" : "=l"(dn) : "f"(a[n]));
      asm("fma.rn.f32x2 %0, %1, %2, %0;" : "+l"(A01[n]) : "l"(w01), "l"(dn));
      asm("fma.rn.f32x2 %0, %1, %2, %0;" : "+l"(A23[n]) : "l"(w23), "l"(dn));
    }
  }

  float A0[8], A1[8], A2[8], A3[8];
#pragma unroll
  for (int n = 0; n < 8; n++) {
    asm("mov.b64 {%0,%1}, %2;" : "=f"(A0[n]), "=f"(A1[n]) : "l"(A01[n]));
    asm("mov.b64 {%0,%1}, %2;" : "=f"(A2[n]), "=f"(A3[n]) : "l"(A23[n]));
    A0[n] = fmaxf(A0[n], 0.f); A1[n] = fmaxf(A1[n], 0.f);
    A2[n] = fmaxf(A2[n], 0.f); A3[n] = fmaxf(A3[n], 0.f);
  }

  const int p0i = cg*4;
  float4 E0 = *(const float4*)&W3p[(p0i+0)*4];
  float4 E1 = *(const float4*)&W3p[(p0i+1)*4];
  float4 E2 = *(const float4*)&W3p[(p0i+2)*4];
  float4 E3 = *(const float4*)&W3p[(p0i+3)*4];

  float p0[8], p1[8], p2[8];
#pragma unroll
  for (int n = 0; n < 8; n++) {
    p0[n] = fmaf(A0[n],E0.x, fmaf(A1[n],E1.x, fmaf(A2[n],E2.x, A3[n]*E3.x)));
    p1[n] = fmaf(A0[n],E0.y, fmaf(A1[n],E1.y, fmaf(A2[n],E2.y, A3[n]*E3.y)));
    p2[n] = fmaf(A0[n],E0.z, fmaf(A1[n],E1.z, fmaf(A2[n],E2.z, A3[n]*E3.z)));
  }

  // reduce over cg: xor masks {2,4,8,16} keep sample parity
#pragma unroll
  for (int m = 2; m <= 16; m <<= 1) {
#pragma unroll
    for (int n = 0; n < 8; n++) {
      p0[n] += __shfl_xor_sync(0xffffffffu, p0[n], m);
      p1[n] += __shfl_xor_sync(0xffffffffu, p1[n], m);
      p2[n] += __shfl_xor_sync(0xffffffffu, p2[n], m);
    }
  }
  if (cg == 0 && (u == 0 || ok1)) {
    float* d = (u ? sc1 : sc0) + SLATP;
#pragma unroll
    for (int n = 0; n < 8; n++) {
      d[n*3 + 0] = p0[n]; d[n*3 + 1] = p1[n]; d[n*3 + 2] = p2[n];
    }
  }
  __syncwarp();
}

__global__ __launch_bounds__(THREADS, 1)
void gae9_kernel(KParams kp, float* __restrict__ out)
{
  float* ws = smem;
  const int tid = threadIdx.x;

  // ================= stage weights =================
  cpy(ws+EW1, kp.w[0], 192, tid); cpy(ws+EB1, kp.w[1], 64, tid);
  cpy(ws+EW2P, kp.w[2], 4096, tid);
  cpy(ws+EB2P, kp.w[3], 64, tid);
  { const float* w4 = kp.w[4];
    for (int i = tid; i < 256; i += THREADS) {
      int c = i >> 2, l = i & 3;
      ws[EW3P + i] = (l < 3) ? w4[c*3 + l] : 0.f;
    } }
  if (tid < 4) ws[EB3+tid] = (tid < 3) ? kp.w[5][tid] : 0.f;
  cpy(ws+G1WL, kp.w[6], 192, tid);  cpy(ws+G1BL, kp.w[7], 64, tid);
  cpy(ws+G1WR, kp.w[8], 192, tid);  cpy(ws+G1BR, kp.w[9], 64, tid);
  cpy(ws+G1WE, kp.w[10], 64, tid);  cpy(ws+G1ATT, kp.w[11], 64, tid);
  cpy(ws+G1BIAS, kp.w[12], 64, tid);
  { const float* wl = kp.w[13]; const float* wr = kp.w[15];
    for (int i = tid; i < 192; i += THREADS) {
      int k = i / 3, l = i - k*3;
      ws[G2WLT + l*64 + k] = wl[i];
      ws[G2WRT + l*64 + k] = wr[i];
    } }
  if (tid < 4) {
    ws[G2BL4 + tid]   = (tid < 3) ? kp.w[14][tid] : 0.f;
    ws[G2BR4 + tid]   = (tid < 3) ? kp.w[16][tid] : 0.f;
    ws[G2WE4 + tid]   = (tid < 3) ? kp.w[17][tid] : 0.f;
    ws[G2ATT4 + tid]  = (tid < 3) ? kp.w[18][tid] : 0.f;
    ws[G2BIAS4 + tid] = (tid < 3) ? kp.w[19][tid] : 0.f;
  }
  if (tid < 12) ws[SKW+tid] = (tid < 9) ? kp.w[20][tid] : 0.f;
  if (tid < 4)  ws[SKB+tid] = (tid < 3) ? kp.w[21][tid] : 0.f;
  cpy(ws+DW1, kp.w[22], 192, tid); cpy(ws+DB1, kp.w[23], 64, tid);
  cpy(ws+DW2P, kp.w[24], 4096, tid);
  cpy(ws+DB2P, kp.w[25], 64, tid);
  { const float* w26 = kp.w[26];
    for (int i = tid; i < 256; i += THREADS) {
      int c = i >> 2, l = i & 3;
      ws[DW3P + i] = (l < 3) ? w26[c*3 + l] : 0.f;
    } }
  if (tid < 4) ws[DB3+tid] = (tid < 3) ? kp.w[27][tid] : 0.f;

  const int g = tid >> 5;
  const int t = tid & 31;
  const int Btot = kp.B;
  const bool ok1 = (g < WARPS-1);              // warp18's 2nd sample is dead
  const int slot1 = ok1 ? (2*g + 1) : 2*g;     // alias warp18's slot1 onto slot0
  float* sc0 = smem + WTOT + (2*g)*SPER;
  float* sc1 = smem + WTOT + slot1*SPER;
  const int s0 = blockIdx.x*SPB + 2*g;
  const int s1 = s0 + 1;
  const bool v0 = (s0 < Btot);
  const bool v1 = ok1 && (s1 < Btot);

  if (t < 8) {
    sc0[SX + t] = kp.x[(v0 ? s0 : Btot-1)*8 + t];
    if (ok1) sc1[SX + t] = kp.x[(v1 ? s1 : Btot-1)*8 + t];
  }
  __syncthreads();

  const int n3 = t / 3, l3 = t - n3*3;

  // ================= encoder L1 (3->64), per sample, layout [c][n] stride 8 ====
  {
    float wn1 = ws[EW1+64+t],    wx1 = ws[EW1+128+t],    bb1 = ws[EB1+t];
    float wn2 = ws[EW1+64+t+32], wx2 = ws[EW1+128+t+32], bb2 = ws[EB1+t+32];
#pragma unroll
    for (int u = 0; u < 2; u++) {
      float* sc = u ? sc1 : sc0;
      if (u && !ok1) break;
      float va[8], vb[8];
#pragma unroll
      for (int n = 0; n < 8; n++) {
        float xn = sc[SX + n];
        va[n] = fmaxf(fmaf(xn, wx1, fmaf((float)n, wn1, bb1)), 0.f);
        vb[n] = fmaxf(fmaf(xn, wx2, fmaf((float)n, wn2, bb2)), 0.f);
      }
      *(float4*)&sc[SA + t*8]          = make_float4(va[0],va[1],va[2],va[3]);
      *(float4*)&sc[SA + t*8 + 4]      = make_float4(va[4],va[5],va[6],va[7]);
      *(float4*)&sc[SA + (t+32)*8]     = make_float4(vb[0],vb[1],vb[2],vb[3]);
      *(float4*)&sc[SA + (t+32)*8 + 4] = make_float4(vb[4],vb[5],vb[6],vb[7]);
    }
  }
  __syncwarp();

  // ================= encoder L2+L3 (dual-sample) =================
  mlp64_dual(sc0 + SA, sc1 + SA, sc0, sc1, ok1, ws + EW2P, ws + EB2P, ws + EW3P, t);

#pragma unroll
  for (int u = 0; u < 2; u++) {
    float* sc = u ? sc1 : sc0;
    if ((u == 0 || ok1) && t < 24)
      sc[SLAT + n3*4 + l3] = sc[SLATP + t] + ws[EB3 + l3];
  }
  __syncwarp();

  // ================= normalize -> vis + xp/vis outputs =================
#pragma unroll
  for (int u = 0; u < 2; u++) {
    float* sc = u ? sc1 : sc0;
    const bool okU = (u == 0) || ok1;
    const bool vU = u ? v1 : v0;
    const int sU = u ? s1 : s0;
    int ln_l = t >> 3, ln_n = t & 7;
    float v = sc[SLAT + ln_n*4 + ((ln_l < 3) ? ln_l : 0)];
    float sm = v;
    sm += __shfl_xor_sync(0xffffffffu, sm, 1);
    sm += __shfl_xor_sync(0xffffffffu, sm, 2);
    sm += __shfl_xor_sync(0xffffffffu, sm, 4);
    float c = v - sm*0.125f;
    float vv = c*c;
    vv += __shfl_xor_sync(0xffffffffu, vv, 1);
    vv += __shfl_xor_sync(0xffffffffu, vv, 2);
    vv += __shfl_xor_sync(0xffffffffu, vv, 4);
    float inv = 1.f / (sqrtf(vv * (1.f/7.f)) + 1e-8f);
    float visv = c*inv;
    if (t < 24) {
      if (okU) sc[SVIS + ln_n*4 + ln_l] = visv;
      if (vU) {
        out[2*Btot*24 + sU*24 + ln_n*3 + ln_l] = visv;
        float xpv = (l3 == 0) ? 0.f : ((l3 == 1) ? (float)n3 : sc[SX + n3]);
        out[sU*24 + t] = xpv;
      }
    }
  }
  __syncwarp();

  // ================= Gabriel graph (2 pairs per lane per sample) =================
#pragma unroll
  for (int u = 0; u < 2; u++) {
    float* sc = u ? sc1 : sc0;
    const bool okU = (u == 0) || ok1;
    const bool vU = u ? v1 : v0;
    const int sU = u ? s1 : s0;
    float4 Pv[8];
#pragma unroll
    for (int n = 0; n < 8; n++) Pv[n] = *(const float4*)&sc[SVIS + n*4];
    int i0 = t >> 3, j0 = t & 7;
    int i1 = (t + 32) >> 3;
    float4 pi0 = Pv[i0], pj0 = Pv[j0], pi1 = Pv[i1];
    float a0, d0, a1, d1;
    {
      float mx=(pi0.x+pj0.x)*0.5f, my=(pi0.y+pj0.y)*0.5f, mz=(pi0.z+pj0.z)*0.5f;
      float rx=pi0.x-mx, ry=pi0.y-my, rz=pi0.z-mz;
      float r2 = rx*rx+ry*ry+rz*rz;
      bool viol = false;
#pragma unroll
      for (int k = 0; k < 8; k++) {
        float ex=Pv[k].x-mx, ey=Pv[k].y-my, ez=Pv[k].z-mz;
        float d2 = ex*ex+ey*ey+ez*ez;
        viol |= (k != i0) && (k != j0) && (d2 < r2);
      }
      a0 = (!viol && (i0 != j0)) ? 1.f : 0.f;
      float dx=pi0.x-pj0.x, dy=pi0.y-pj0.y, dz=pi0.z-pj0.z;
      d0 = sqrtf(dx*dx+dy*dy+dz*dz + 1e-30f);
    }
    {
      float mx=(pi1.x+pj0.x)*0.5f, my=(pi1.y+pj0.y)*0.5f, mz=(pi1.z+pj0.z)*0.5f;
      float rx=pi1.x-mx, ry=pi1.y-my, rz=pi1.z-mz;
      float r2 = rx*rx+ry*ry+rz*rz;
      bool viol = false;
#pragma unroll
      for (int k = 0; k < 8; k++) {
        float ex=Pv[k].x-mx, ey=Pv[k].y-my, ez=Pv[k].z-mz;
        float d2 = ex*ex+ey*ey+ez*ez;
        viol |= (k != i1) && (k != j0) && (d2 < r2);
      }
      a1 = (!viol && (i1 != j0)) ? 1.f : 0.f;
      float dx=pi1.x-pj0.x, dy=pi1.y-pj0.y, dz=pi1.z-pj0.z;
      d1 = sqrtf(dx*dx+dy*dy+dz*dz + 1e-30f);
    }
    float as = a0 + a1, ds = a0*d0 + a1*d1;
#pragma unroll
    for (int m = 16; m; m >>= 1) {
      as += __shfl_xor_sync(0xffffffffu, as, m);
      ds += __shfl_xor_sync(0xffffffffu, ds, m);
    }
    float ma = ds / fmaxf(as, 1.f);
    if (okU) {
      // merged eat/mask: masked-out pairs stored as -1.0
      sc[SEM + t]      = (i0 == j0) ? ma : (a0 > 0.f ? d0 : -1.f);
      sc[SEM + t + 32] = (i1 == j0) ? ma : (a1 > 0.f ? d1 : -1.f);
    }
    if (vU) {
      out[3*Btot*24 + sU*64 + t]      = a0;
      out[3*Btot*24 + sU*64 + t + 32] = a1;
    }
  }
  __syncwarp();

  // ================= GAT1 linear (3->64 xl, xr)  [n][c] stride 68 =================
  {
    float wl0a=ws[G1WL+t],    wl1a=ws[G1WL+64+t],    wl2a=ws[G1WL+128+t],    bla=ws[G1BL+t];
    float wl0b=ws[G1WL+t+32], wl1b=ws[G1WL+64+t+32], wl2b=ws[G1WL+128+t+32], blb=ws[G1BL+t+32];
    float wr0a=ws[G1WR+t],    wr1a=ws[G1WR+64+t],    wr2a=ws[G1WR+128+t],    bra=ws[G1BR+t];
    float wr0b=ws[G1WR+t+32], wr1b=ws[G1WR+64+t+32], wr2b=ws[G1WR+128+t+32], brb=ws[G1BR+t+32];
#pragma unroll
    for (int u = 0; u < 2; u++) {
      float* sc = u ? sc1 : sc0;
      if (u && !ok1) break;
#pragma unroll
      for (int n = 0; n < 8; n++) {
        float4 la = *(const float4*)&sc[SLAT + n*4];
        sc[SXL + n*68 + t]      = fmaf(la.x, wl0a, fmaf(la.y, wl1a, fmaf(la.z, wl2a, bla)));
        sc[SXL + n*68 + t + 32] = fmaf(la.x, wl0b, fmaf(la.y, wl1b, fmaf(la.z, wl2b, blb)));
        sc[SXR + n*68 + t]      = fmaf(la.x, wr0a, fmaf(la.y, wr1a, fmaf(la.z, wr2a, bra)));
        sc[SXR + n*68 + t + 32] = fmaf(la.x, wr0b, fmaf(la.y, wr1b, fmaf(la.z, wr2b, brb)));
      }
    }
  }
  __syncwarp();

  // ================= GAT1 edge scores + softmax (pairs 2t, 2t+1) =================
#pragma unroll
  for (int u = 0; u < 2; u++) {
    float* sc = u ? sc1 : sc0;
    const bool okU = (u == 0) || ok1;
    const int i = t >> 2;
    const int jj = (t & 3) * 2;
    const float* xr = sc + SXR + i*68;
    const float* xa = sc + SXL + jj*68;
    float2 em = *(const float2*)&sc[SEM + 2*t];
    float mk0 = (em.x >= 0.f) ? 1.f : 0.f;
    float mk1 = (em.y >= 0.f) ? 1.f : 0.f;
    float acc0 = 0.f, acc1 = 0.f;
#pragma unroll 8
    for (int c = 0; c < 64; c += 4) {
      float4 r  = *(const float4*)&xr[c];
      float4 l0 = *(const float4*)&xa[c];
      float4 l1 = *(const float4*)&xa[c + 68];
      float4 we = *(const float4*)&ws[G1WE + c];
      float4 at = *(const float4*)&ws[G1ATT + c];
      acc0 = fmaf(lrelu(fmaf(em.x, we.x, r.x) + l0.x), at.x, acc0);
      acc1 = fmaf(lrelu(fmaf(em.y, we.x, r.x) + l1.x), at.x, acc1);
      acc0 = fmaf(lrelu(fmaf(em.x, we.y, r.y) + l0.y), at.y, acc0);
      acc1 = fmaf(lrelu(fmaf(em.y, we.y, r.y) + l1.y), at.y, acc1);
      acc0 = fmaf(lrelu(fmaf(em.x, we.z, r.z) + l0.z), at.z, acc0);
      acc1 = fmaf(lrelu(fmaf(em.y, we.z, r.z) + l1.z), at.z, acc1);
      acc0 = fmaf(lrelu(fmaf(em.x, we.w, r.w) + l0.w), at.w, acc0);
      acc1 = fmaf(lrelu(fmaf(em.y, we.w, r.w) + l1.w), at.w, acc1);
    }
    float e0 = (mk0 != 0.f) ? acc0 : -1e30f;
    float e1 = (mk1 != 0.f) ? acc1 : -1e30f;
    float m = fmaxf(e0, e1);
    m = fmaxf(m, __shfl_xor_sync(0xffffffffu, m, 1));
    m = fmaxf(m, __shfl_xor_sync(0xffffffffu, m, 2));
    float x0 = __expf(e0 - m), x1 = __expf(e1 - m);
    float sden = x0 + x1;
    sden += __shfl_xor_sync(0xffffffffu, sden, 1);
    sden += __shfl_xor_sync(0xffffffffu, sden, 2);
    float inv = 1.f / sden;
    if (okU) *(float2*)&sc[SALPHA + 2*t] = make_float2(x0*inv*mk0, x1*inv*mk1);
  }
  __syncwarp();

  // ================= GAT1 aggregation -> h1 (into SXR), relu =================
#pragma unroll
  for (int u = 0; u < 2; u++) {
    float* sc = u ? sc1 : sc0;
    if (u && !ok1) break;
    float acc1[8], acc2[8];
    float b1 = ws[G1BIAS + t], b2 = ws[G1BIAS + t + 32];
#pragma unroll
    for (int i = 0; i < 8; i++) { acc1[i] = b1; acc2[i] = b2; }
#pragma unroll
    for (int j = 0; j < 8; j += 2) {
      float xv1a = sc[SXL + j*68 + t],       xv2a = sc[SXL + j*68 + t + 32];
      float xv1b = sc[SXL + (j+1)*68 + t],   xv2b = sc[SXL + (j+1)*68 + t + 32];
#pragma unroll
      for (int i = 0; i < 8; i++) {
        float2 al = *(const float2*)&sc[SALPHA + i*8 + j];
        acc1[i] = fmaf(al.x, xv1a, fmaf(al.y, xv1b, acc1[i]));
        acc2[i] = fmaf(al.x, xv2a, fmaf(al.y, xv2b, acc2[i]));
      }
    }
    __syncwarp();
#pragma unroll
    for (int i = 0; i < 8; i++) {
      sc[SXR + i*68 + t]      = fmaxf(acc1[i], 0.f);
      sc[SXR + i*68 + t + 32] = fmaxf(acc2[i], 0.f);
    }
  }
  __syncwarp();

  // ================= GAT2 linear (64->3 xl2, xr2) =================
#pragma unroll
  for (int u = 0; u < 2; u++) {
    float* sc = u ? sc1 : sc0;
    if (u && !ok1) break;
    if (t < 24) {
      float a1 = ws[G2BL4 + l3], a2 = ws[G2BR4 + l3];
      const float* h1p = sc + SXR + n3*68;
#pragma unroll
      for (int c = 0; c < 64; c += 4) {
        float4 hh = *(const float4*)&h1p[c];
        float4 wl = *(const float4*)&ws[G2WLT + l3*64 + c];
        float4 wr = *(const float4*)&ws[G2WRT + l3*64 + c];
        a1 = fmaf(hh.x, wl.x, fmaf(hh.y, wl.y, fmaf(hh.z, wl.z, fmaf(hh.w, wl.w, a1))));
        a2 = fmaf(hh.x, wr.x, fmaf(hh.y, wr.y, fmaf(hh.z, wr.z, fmaf(hh.w, wr.w, a2))));
      }
      sc[SXL2 + n3*4 + l3] = a1;
      sc[SXR2 + n3*4 + l3] = a2;
    }
  }
  __syncwarp();

  // ================= GAT2 edge scores + softmax =================
#pragma unroll
  for (int u = 0; u < 2; u++) {
    float* sc = u ? sc1 : sc0;
    const bool okU = (u == 0) || ok1;
    const int i = t >> 2;
    const int jj = (t & 3) * 2;
    float4 r   = *(const float4*)&sc[SXR2 + i*4];
    float4 l0  = *(const float4*)&sc[SXL2 + jj*4];
    float4 l1  = *(const float4*)&sc[SXL2 + (jj+1)*4];
    float4 we  = *(const float4*)&ws[G2WE4];
    float4 at  = *(const float4*)&ws[G2ATT4];
    float2 em = *(const float2*)&sc[SEM + 2*t];
    float mk0 = (em.x >= 0.f) ? 1.f : 0.f;
    float mk1 = (em.y >= 0.f) ? 1.f : 0.f;
    float acc0 = 0.f, acc1 = 0.f;
    acc0 = fmaf(lrelu(fmaf(em.x, we.x, r.x) + l0.x), at.x, acc0);
    acc1 = fmaf(lrelu(fmaf(em.y, we.x, r.x) + l1.x), at.x, acc1);
    acc0 = fmaf(lrelu(fmaf(em.x, we.y, r.y) + l0.y), at.y, acc0);
    acc1 = fmaf(lrelu(fmaf(em.y, we.y, r.y) + l1.y), at.y, acc1);
    acc0 = fmaf(lrelu(fmaf(em.x, we.z, r.z) + l0.z), at.z, acc0);
    acc1 = fmaf(lrelu(fmaf(em.y, we.z, r.z) + l1.z), at.z, acc1);
    float e0 = (mk0 != 0.f) ? acc0 : -1e30f;
    float e1 = (mk1 != 0.f) ? acc1 : -1e30f;
    float m = fmaxf(e0, e1);
    m = fmaxf(m, __shfl_xor_sync(0xffffffffu, m, 1));
    m = fmaxf(m, __shfl_xor_sync(0xffffffffu, m, 2));
    float x0 = __expf(e0 - m), x1 = __expf(e1 - m);
    float sden = x0 + x1;
    sden += __shfl_xor_sync(0xffffffffu, sden, 1);
    sden += __shfl_xor_sync(0xffffffffu, sden, 2);
    float inv = 1.f / sden;
    if (okU) *(float2*)&sc[SALPHA + 2*t] = make_float2(x0*inv*mk0, x1*inv*mk1);
  }
  __syncwarp();

  // ================= GAT2 aggregation + skip -> combined =================
#pragma unroll
  for (int u = 0; u < 2; u++) {
    float* sc = u ? sc1 : sc0;
    if (u && !ok1) break;
    if (t < 24) {
      float acc = ws[G2BIAS4 + l3];
#pragma unroll
      for (int j = 0; j < 8; j++)
        acc = fmaf(sc[SALPHA + n3*8 + j], sc[SXL2 + j*4 + l3], acc);
      float4 la = *(const float4*)&sc[SLAT + n3*4];
      acc += fmaf(la.x, ws[SKW + l3],
             fmaf(la.y, ws[SKW + 3 + l3],
             fmaf(la.z, ws[SKW + 6 + l3], ws[SKB + l3])));
      sc[SCOMB + n3*4 + l3] = acc;
    }
  }
  __syncwarp();

  // ================= decoder L1 (3->64) =================
  {
    float w0a=ws[DW1+t],    w1a=ws[DW1+64+t],    w2a=ws[DW1+128+t],    ba=ws[DB1+t];
    float w0b=ws[DW1+t+32], w1b=ws[DW1+64+t+32], w2b=ws[DW1+128+t+32], bb=ws[DB1+t+32];
#pragma unroll
    for (int u = 0; u < 2; u++) {
      float* sc = u ? sc1 : sc0;
      if (u && !ok1) break;
      float va[8], vb[8];
#pragma unroll
      for (int n = 0; n < 8; n++) {
        float4 cm = *(const float4*)&sc[SCOMB + n*4];
        va[n] = fmaxf(fmaf(cm.x, w0a, fmaf(cm.y, w1a, fmaf(cm.z, w2a, ba))), 0.f);
        vb[n] = fmaxf(fmaf(cm.x, w0b, fmaf(cm.y, w1b, fmaf(cm.z, w2b, bb))), 0.f);
      }
      *(float4*)&sc[SA + t*8]          = make_float4(va[0],va[1],va[2],va[3]);
      *(float4*)&sc[SA + t*8 + 4]      = make_float4(va[4],va[5],va[6],va[7]);
      *(float4*)&sc[SA + (t+32)*8]     = make_float4(vb[0],vb[1],vb[2],vb[3]);
      *(float4*)&sc[SA + (t+32)*8 + 4] = make_float4(vb[4],vb[5],vb[6],vb[7]);
    }
  }
  __syncwarp();

  // ================= decoder L2+L3 (dual-sample) =================
  mlp64_dual(sc0 + SA, sc1 + SA, sc0, sc1, ok1, ws + DW2P, ws + DB2P, ws + DW3P, t);

#pragma unroll
  for (int u = 0; u < 2; u++) {
    float* sc = u ? sc1 : sc0;
    const bool vU = u ? v1 : v0;
    const int sU = u ? s1 : s0;
    if (vU && t < 24)
      out[Btot*24 + sU*24 + t] = sc[SLATP + t] + ws[DB3 + l3];
  }
}

extern "C" void kernel_launch(void* const* d_in, const int* in_sizes, int n_in,
                              void* d_out, int out_size)
{
  (void)n_in; (void)out_size;
  KParams kp;
  kp.x = (const float*)d_in[0];
  for (int i = 0; i < 28; i++) kp.w[i] = (const float*)d_in[i + 1];
  kp.B = in_sizes[0] / 8;

  cudaFuncSetAttribute(gae9_kernel, cudaFuncAttributeMaxDynamicSharedMemorySize, SMEM_BYTES);
  int grid = (kp.B + SPB - 1) / SPB;
  gae9_kernel<<<grid, THREADS, SMEM_BYTES>>>(kp, (float*)d_out);
}

// round 10
// speedup vs baseline: 1.3018x; 1.0109x over previous
#include <cuda_runtime.h>

#define SPB 37           // samples per block: 18 warps x 2 + warp18 x 1
#define WARPS 19
#define THREADS (WARPS*32)   // 608; grid = ceil(B/37) = 443 -> 3 waves

// ---- weight offsets in shared (floats) ----
enum {
  EW1=0, EB1=192, EW2P=256, EB2P=4352, EW3P=4416, EB3=4672,
  G1WL=4676, G1BL=4868, G1WR=4932, G1BR=5124, G1WE=5188, G1ATT=5252, G1BIAS=5316,
  G2WLT=5380, G2BL4=5572, G2WRT=5576, G2BR4=5768,
  G2WE4=5772, G2ATT4=5776, G2BIAS4=5780,
  SKW=5784, SKB=5796,
  DW1=5800, DB1=5992, DW2P=6056, DB2P=10152, DW3P=10216, DB3=10472,
  WTOT=10476
};
// ---- per-sample scratch (floats); heavy lifetime overlays ----
enum {
  SA=0, SLATP=512, SXL=0, SXR=544, SXL2=0, SXR2=32,
  SEM=1084, SX=1084, SALPHA=1148, SLAT=1212, SVIS=1244, SCOMB=1244,
  SPER=1276
};

#define SMEM_FLOATS (WTOT + SPB*SPER)
#define SMEM_BYTES  (SMEM_FLOATS*4)   // 230,752 B -> 1 block/SM

struct KParams {
  const float* x;
  const float* w[28];
  int B;
};

extern __shared__ float smem[];

__device__ __forceinline__ void cpy(float* dst, const float* src, int n, int tid) {
  for (int i = tid; i < n; i += THREADS) dst[i] = src[i];
}

__device__ __forceinline__ float lrelu(float h) { return fmaxf(h, 0.2f*h); }

__device__ __forceinline__ unsigned sm_u32(const void* p) {
  unsigned a;
  asm("{ .reg .u64 t; cvta.to.shared.u64 t, %1; cvt.u32.u64 %0, t; }"
      : "=r"(a) : "l"(p));
  return a;
}

// Dual-sample 8x64 @ 64x64 + relu + fused (64->3) projection; f32x2 with
// NODE-PAIR packed accumulators: D{c}[p] = {acc(4cg+c,2p), acc(4cg+c,2p+1)}.
// Activation loads arrive naturally packed; only 4 weight splats per k.
// Lane: u = t&1 (sample), cg = t>>1 (channels 4cg..4cg+3), all 8 nodes.
// Warp18 (sc1==sc0) computes duplicates; all smem stores are idempotent.
__device__ __forceinline__ void mlp64_dual(
    const float* __restrict__ in0, const float* __restrict__ in1,
    float* sc0, float* sc1,
    const float* __restrict__ Wp, const float* __restrict__ bp,
    const float* __restrict__ W3p, int t)
{
  const int u = t & 1, cg = t >> 1;
  const unsigned abase = sm_u32(u ? in1 : in0);
  const unsigned wbase = sm_u32(Wp) + cg*16u;

  float4 b4 = *(const float4*)&bp[cg*4];
  unsigned long long D0[4], D1[4], D2[4], D3[4];
  {
    unsigned long long bd0, bd1, bd2, bd3;
    asm("mov.b64 %0, {%1,%1};" : "=l"(bd0) : "f"(b4.x));
    asm("mov.b64 %0, {%1,%1};" : "=l"(bd1) : "f"(b4.y));
    asm("mov.b64 %0, {%1,%1};" : "=l"(bd2) : "f"(b4.z));
    asm("mov.b64 %0, {%1,%1};" : "=l"(bd3) : "f"(b4.w));
#pragma unroll
    for (int p = 0; p < 4; p++) { D0[p]=bd0; D1[p]=bd1; D2[p]=bd2; D3[p]=bd3; }
  }

#pragma unroll 4
  for (int k = 0; k < 64; k++) {
    unsigned aa = abase + (unsigned)(k*32);
    unsigned wa = wbase + (unsigned)(k*256);
    unsigned long long ar0, ar1, ar2, ar3, w01, w23;
    asm("ld.shared.v2.u64 {%0,%1}, [%2];" : "=l"(ar0), "=l"(ar1) : "r"(aa));
    asm("ld.shared.v2.u64 {%0,%1}, [%2];" : "=l"(ar2), "=l"(ar3) : "r"(aa+16u));
    asm("ld.shared.v2.u64 {%0,%1}, [%2];" : "=l"(w01), "=l"(w23) : "r"(wa));
    float w0, w1, w2, w3;
    asm("mov.b64 {%0,%1}, %2;" : "=f"(w0), "=f"(w1) : "l"(w01));
    asm("mov.b64 {%0,%1}, %2;" : "=f"(w2), "=f"(w3) : "l"(w23));
    unsigned long long wd0, wd1, wd2, wd3;
    asm("mov.b64 %0, {%1,%1};" : "=l"(wd0) : "f"(w0));
    asm("mov.b64 %0, {%1,%1};" : "=l"(wd1) : "f"(w1));
    asm("mov.b64 %0, {%1,%1};" : "=l"(wd2) : "f"(w2));
    asm("mov.b64 %0, {%1,%1};" : "=l"(wd3) : "f"(w3));
    asm("fma.rn.f32x2 %0, %1, %2, %0;" : "+l"(D0[0]) : "l"(wd0), "l"(ar0));
    asm("fma.rn.f32x2 %0, %1, %2, %0;" : "+l"(D0[1]) : "l"(wd0), "l"(ar1));
    asm("fma.rn.f32x2 %0, %1, %2, %0;" : "+l"(D0[2]) : "l"(wd0), "l"(ar2));
    asm("fma.rn.f32x2 %0, %1, %2, %0;" : "+l"(D0[3]) : "l"(wd0), "l"(ar3));
    asm("fma.rn.f32x2 %0, %1, %2, %0;" : "+l"(D1[0]) : "l"(wd1), "l"(ar0));
    asm("fma.rn.f32x2 %0, %1, %2, %0;" : "+l"(D1[1]) : "l"(wd1), "l"(ar1));
    asm("fma.rn.f32x2 %0, %1, %2, %0;" : "+l"(D1[2]) : "l"(wd1), "l"(ar2));
    asm("fma.rn.f32x2 %0, %1, %2, %0;" : "+l"(D1[3]) : "l"(wd1), "l"(ar3));
    asm("fma.rn.f32x2 %0, %1, %2, %0;" : "+l"(D2[0]) : "l"(wd2), "l"(ar0));
    asm("fma.rn.f32x2 %0, %1, %2, %0;" : "+l"(D2[1]) : "l"(wd2), "l"(ar1));
    asm("fma.rn.f32x2 %0, %1, %2, %0;" : "+l"(D2[2]) : "l"(wd2), "l"(ar2));
    asm("fma.rn.f32x2 %0, %1, %2, %0;" : "+l"(D2[3]) : "l"(wd2), "l"(ar3));
    asm("fma.rn.f32x2 %0, %1, %2, %0;" : "+l"(D3[0]) : "l"(wd3), "l"(ar0));
    asm("fma.rn.f32x2 %0, %1, %2, %0;" : "+l"(D3[1]) : "l"(wd3), "l"(ar1));
    asm("fma.rn.f32x2 %0, %1, %2, %0;" : "+l"(D3[2]) : "l"(wd3), "l"(ar2));
    asm("fma.rn.f32x2 %0, %1, %2, %0;" : "+l"(D3[3]) : "l"(wd3), "l"(ar3));
  }

  float A0[8], A1[8], A2[8], A3[8];
#pragma unroll
  for (int p = 0; p < 4; p++) {
    asm("mov.b64 {%0,%1}, %2;" : "=f"(A0[2*p]), "=f"(A0[2*p+1]) : "l"(D0[p]));
    asm("mov.b64 {%0,%1}, %2;" : "=f"(A1[2*p]), "=f"(A1[2*p+1]) : "l"(D1[p]));
    asm("mov.b64 {%0,%1}, %2;" : "=f"(A2[2*p]), "=f"(A2[2*p+1]) : "l"(D2[p]));
    asm("mov.b64 {%0,%1}, %2;" : "=f"(A3[2*p]), "=f"(A3[2*p+1]) : "l"(D3[p]));
  }
#pragma unroll
  for (int n = 0; n < 8; n++) {
    A0[n] = fmaxf(A0[n], 0.f); A1[n] = fmaxf(A1[n], 0.f);
    A2[n] = fmaxf(A2[n], 0.f); A3[n] = fmaxf(A3[n], 0.f);
  }

  const int p0i = cg*4;
  float4 E0 = *(const float4*)&W3p[(p0i+0)*4];
  float4 E1 = *(const float4*)&W3p[(p0i+1)*4];
  float4 E2 = *(const float4*)&W3p[(p0i+2)*4];
  float4 E3 = *(const float4*)&W3p[(p0i+3)*4];

  float p0[8], p1[8], p2[8];
#pragma unroll
  for (int n = 0; n < 8; n++) {
    p0[n] = fmaf(A0[n],E0.x, fmaf(A1[n],E1.x, fmaf(A2[n],E2.x, A3[n]*E3.x)));
    p1[n] = fmaf(A0[n],E0.y, fmaf(A1[n],E1.y, fmaf(A2[n],E2.y, A3[n]*E3.y)));
    p2[n] = fmaf(A0[n],E0.z, fmaf(A1[n],E1.z, fmaf(A2[n],E2.z, A3[n]*E3.z)));
  }

#pragma unroll
  for (int m = 2; m <= 16; m <<= 1) {
#pragma unroll
    for (int n = 0; n < 8; n++) {
      p0[n] += __shfl_xor_sync(0xffffffffu, p0[n], m);
      p1[n] += __shfl_xor_sync(0xffffffffu, p1[n], m);
      p2[n] += __shfl_xor_sync(0xffffffffu, p2[n], m);
    }
  }
  if (cg == 0) {                 // lanes 0 (u=0) and 1 (u=1); warp18 idempotent
    float* d = (u ? sc1 : sc0) + SLATP;
#pragma unroll
    for (int n = 0; n < 8; n++) {
      d[n*3 + 0] = p0[n]; d[n*3 + 1] = p1[n]; d[n*3 + 2] = p2[n];
    }
  }
  __syncwarp();
}

__global__ __launch_bounds__(THREADS, 1)
void gae10_kernel(KParams kp, float* __restrict__ out)
{
  float* ws = smem;
  const int tid = threadIdx.x;

  // ================= stage weights =================
  cpy(ws+EW1, kp.w[0], 192, tid); cpy(ws+EB1, kp.w[1], 64, tid);
  cpy(ws+EW2P, kp.w[2], 4096, tid);
  cpy(ws+EB2P, kp.w[3], 64, tid);
  { const float* w4 = kp.w[4];
    for (int i = tid; i < 256; i += THREADS) {
      int c = i >> 2, l = i & 3;
      ws[EW3P + i] = (l < 3) ? w4[c*3 + l] : 0.f;
    } }
  if (tid < 4) ws[EB3+tid] = (tid < 3) ? kp.w[5][tid] : 0.f;
  cpy(ws+G1WL, kp.w[6], 192, tid);  cpy(ws+G1BL, kp.w[7], 64, tid);
  cpy(ws+G1WR, kp.w[8], 192, tid);  cpy(ws+G1BR, kp.w[9], 64, tid);
  cpy(ws+G1WE, kp.w[10], 64, tid);  cpy(ws+G1ATT, kp.w[11], 64, tid);
  cpy(ws+G1BIAS, kp.w[12], 64, tid);
  { const float* wl = kp.w[13]; const float* wr = kp.w[15];
    for (int i = tid; i < 192; i += THREADS) {
      int k = i / 3, l = i - k*3;
      ws[G2WLT + l*64 + k] = wl[i];
      ws[G2WRT + l*64 + k] = wr[i];
    } }
  if (tid < 4) {
    ws[G2BL4 + tid]   = (tid < 3) ? kp.w[14][tid] : 0.f;
    ws[G2BR4 + tid]   = (tid < 3) ? kp.w[16][tid] : 0.f;
    ws[G2WE4 + tid]   = (tid < 3) ? kp.w[17][tid] : 0.f;
    ws[G2ATT4 + tid]  = (tid < 3) ? kp.w[18][tid] : 0.f;
    ws[G2BIAS4 + tid] = (tid < 3) ? kp.w[19][tid] : 0.f;
  }
  if (tid < 12) ws[SKW+tid] = (tid < 9) ? kp.w[20][tid] : 0.f;
  if (tid < 4)  ws[SKB+tid] = (tid < 3) ? kp.w[21][tid] : 0.f;
  cpy(ws+DW1, kp.w[22], 192, tid); cpy(ws+DB1, kp.w[23], 64, tid);
  cpy(ws+DW2P, kp.w[24], 4096, tid);
  cpy(ws+DB2P, kp.w[25], 64, tid);
  { const float* w26 = kp.w[26];
    for (int i = tid; i < 256; i += THREADS) {
      int c = i >> 2, l = i & 3;
      ws[DW3P + i] = (l < 3) ? w26[c*3 + l] : 0.f;
    } }
  if (tid < 4) ws[DB3+tid] = (tid < 3) ? kp.w[27][tid] : 0.f;

  const int g = tid >> 5;
  const int t = tid & 31;
  const int Btot = kp.B;
  const bool ok1 = (g < WARPS-1);
  const int slot1 = ok1 ? (2*g + 1) : 2*g;     // warp18: sc1 aliases sc0
  float* sc0 = smem + WTOT + (2*g)*SPER;
  float* sc1 = smem + WTOT + slot1*SPER;
  const int s0 = blockIdx.x*SPB + 2*g;
  const int s1 = s0 + 1;
  const bool v0 = (s0 < Btot);
  const bool v1 = ok1 && (s1 < Btot);

  if (t < 8) {
    sc0[SX + t] = kp.x[(v0 ? s0 : Btot-1)*8 + t];
    if (ok1) sc1[SX + t] = kp.x[(v1 ? s1 : Btot-1)*8 + t];
  }
  __syncthreads();

  const int n3 = t / 3, l3 = t - n3*3;

  // ================= encoder L1 (3->64), layout [c][n] stride 8 =================
  {
    float wn1 = ws[EW1+64+t],    wx1 = ws[EW1+128+t],    bb1 = ws[EB1+t];
    float wn2 = ws[EW1+64+t+32], wx2 = ws[EW1+128+t+32], bb2 = ws[EB1+t+32];
#pragma unroll
    for (int u = 0; u < 2; u++) {
      float* sc = u ? sc1 : sc0;
      float va[8], vb[8];
#pragma unroll
      for (int n = 0; n < 8; n++) {
        float xn = sc[SX + n];
        va[n] = fmaxf(fmaf(xn, wx1, fmaf((float)n, wn1, bb1)), 0.f);
        vb[n] = fmaxf(fmaf(xn, wx2, fmaf((float)n, wn2, bb2)), 0.f);
      }
      *(float4*)&sc[SA + t*8]          = make_float4(va[0],va[1],va[2],va[3]);
      *(float4*)&sc[SA + t*8 + 4]      = make_float4(va[4],va[5],va[6],va[7]);
      *(float4*)&sc[SA + (t+32)*8]     = make_float4(vb[0],vb[1],vb[2],vb[3]);
      *(float4*)&sc[SA + (t+32)*8 + 4] = make_float4(vb[4],vb[5],vb[6],vb[7]);
    }
  }
  __syncwarp();

  // ================= encoder L2+L3 (dual-sample) =================
  mlp64_dual(sc0 + SA, sc1 + SA, sc0, sc1, ws + EW2P, ws + EB2P, ws + EW3P, t);

#pragma unroll
  for (int u = 0; u < 2; u++) {
    float* sc = u ? sc1 : sc0;
    if (t < 24) sc[SLAT + n3*4 + l3] = sc[SLATP + t] + ws[EB3 + l3];
  }
  __syncwarp();

  // ================= normalize -> vis + xp/vis outputs =================
#pragma unroll
  for (int u = 0; u < 2; u++) {
    float* sc = u ? sc1 : sc0;
    const bool vU = u ? v1 : v0;
    const int sU = u ? s1 : s0;
    int ln_l = t >> 3, ln_n = t & 7;
    float v = sc[SLAT + ln_n*4 + ((ln_l < 3) ? ln_l : 0)];
    float sm = v;
    sm += __shfl_xor_sync(0xffffffffu, sm, 1);
    sm += __shfl_xor_sync(0xffffffffu, sm, 2);
    sm += __shfl_xor_sync(0xffffffffu, sm, 4);
    float c = v - sm*0.125f;
    float vv = c*c;
    vv += __shfl_xor_sync(0xffffffffu, vv, 1);
    vv += __shfl_xor_sync(0xffffffffu, vv, 2);
    vv += __shfl_xor_sync(0xffffffffu, vv, 4);
    float inv = 1.f / (sqrtf(vv * (1.f/7.f)) + 1e-8f);
    float visv = c*inv;
    if (t < 24) {
      sc[SVIS + ln_n*4 + ln_l] = visv;
      if (vU) {
        out[2*Btot*24 + sU*24 + ln_n*3 + ln_l] = visv;
        float xpv = (l3 == 0) ? 0.f : ((l3 == 1) ? (float)n3 : sc[SX + n3]);
        out[sU*24 + t] = xpv;
      }
    }
  }
  __syncwarp();

  // ================= Gabriel graph (2 pairs per lane per sample) =================
#pragma unroll
  for (int u = 0; u < 2; u++) {
    float* sc = u ? sc1 : sc0;
    const bool vU = u ? v1 : v0;
    const int sU = u ? s1 : s0;
    float4 Pv[8];
#pragma unroll
    for (int n = 0; n < 8; n++) Pv[n] = *(const float4*)&sc[SVIS + n*4];
    int i0 = t >> 3, j0 = t & 7;
    int i1 = (t + 32) >> 3;
    float4 pi0 = Pv[i0], pj0 = Pv[j0], pi1 = Pv[i1];
    float a0, d0, a1, d1;
    {
      float mx=(pi0.x+pj0.x)*0.5f, my=(pi0.y+pj0.y)*0.5f, mz=(pi0.z+pj0.z)*0.5f;
      float rx=pi0.x-mx, ry=pi0.y-my, rz=pi0.z-mz;
      float r2 = rx*rx+ry*ry+rz*rz;
      bool viol = false;
#pragma unroll
      for (int k = 0; k < 8; k++) {
        float ex=Pv[k].x-mx, ey=Pv[k].y-my, ez=Pv[k].z-mz;
        float d2 = ex*ex+ey*ey+ez*ez;
        viol |= (k != i0) && (k != j0) && (d2 < r2);
      }
      a0 = (!viol && (i0 != j0)) ? 1.f : 0.f;
      float dx=pi0.x-pj0.x, dy=pi0.y-pj0.y, dz=pi0.z-pj0.z;
      d0 = sqrtf(dx*dx+dy*dy+dz*dz + 1e-30f);
    }
    {
      float mx=(pi1.x+pj0.x)*0.5f, my=(pi1.y+pj0.y)*0.5f, mz=(pi1.z+pj0.z)*0.5f;
      float rx=pi1.x-mx, ry=pi1.y-my, rz=pi1.z-mz;
      float r2 = rx*rx+ry*ry+rz*rz;
      bool viol = false;
#pragma unroll
      for (int k = 0; k < 8; k++) {
        float ex=Pv[k].x-mx, ey=Pv[k].y-my, ez=Pv[k].z-mz;
        float d2 = ex*ex+ey*ey+ez*ez;
        viol |= (k != i1) && (k != j0) && (d2 < r2);
      }
      a1 = (!viol && (i1 != j0)) ? 1.f : 0.f;
      float dx=pi1.x-pj0.x, dy=pi1.y-pj0.y, dz=pi1.z-pj0.z;
      d1 = sqrtf(dx*dx+dy*dy+dz*dz + 1e-30f);
    }
    float as = a0 + a1, ds = a0*d0 + a1*d1;
#pragma unroll
    for (int m = 16; m; m >>= 1) {
      as += __shfl_xor_sync(0xffffffffu, as, m);
      ds += __shfl_xor_sync(0xffffffffu, ds, m);
    }
    float ma = ds / fmaxf(as, 1.f);
    sc[SEM + t]      = (i0 == j0) ? ma : (a0 > 0.f ? d0 : -1.f);
    sc[SEM + t + 32] = (i1 == j0) ? ma : (a1 > 0.f ? d1 : -1.f);
    if (vU) {
      out[3*Btot*24 + sU*64 + t]      = a0;
      out[3*Btot*24 + sU*64 + t + 32] = a1;
    }
  }
  __syncwarp();

  // ========= GAT1 linear (3->64 xl, xr), channel-pair lanes, float2 stores =====
  {
    float2 wl0 = *(const float2*)&ws[G1WL + 2*t];
    float2 wl1 = *(const float2*)&ws[G1WL + 64 + 2*t];
    float2 wl2 = *(const float2*)&ws[G1WL + 128 + 2*t];
    float2 bl  = *(const float2*)&ws[G1BL + 2*t];
    float2 wr0 = *(const float2*)&ws[G1WR + 2*t];
    float2 wr1 = *(const float2*)&ws[G1WR + 64 + 2*t];
    float2 wr2 = *(const float2*)&ws[G1WR + 128 + 2*t];
    float2 br  = *(const float2*)&ws[G1BR + 2*t];
#pragma unroll
    for (int u = 0; u < 2; u++) {
      float* sc = u ? sc1 : sc0;
#pragma unroll
      for (int n = 0; n < 8; n++) {
        float4 la = *(const float4*)&sc[SLAT + n*4];
        float2 xl, xr;
        xl.x = fmaf(la.x, wl0.x, fmaf(la.y, wl1.x, fmaf(la.z, wl2.x, bl.x)));
        xl.y = fmaf(la.x, wl0.y, fmaf(la.y, wl1.y, fmaf(la.z, wl2.y, bl.y)));
        xr.x = fmaf(la.x, wr0.x, fmaf(la.y, wr1.x, fmaf(la.z, wr2.x, br.x)));
        xr.y = fmaf(la.x, wr0.y, fmaf(la.y, wr1.y, fmaf(la.z, wr2.y, br.y)));
        *(float2*)&sc[SXL + n*68 + 2*t] = xl;
        *(float2*)&sc[SXR + n*68 + 2*t] = xr;
      }
    }
  }
  __syncwarp();

  // ================= GAT1 edge scores + softmax (pairs 2t, 2t+1) =================
#pragma unroll
  for (int u = 0; u < 2; u++) {
    float* sc = u ? sc1 : sc0;
    const int i = t >> 2;
    const int jj = (t & 3) * 2;
    const float* xr = sc + SXR + i*68;
    const float* xa = sc + SXL + jj*68;
    float2 em = *(const float2*)&sc[SEM + 2*t];
    float mk0 = (em.x >= 0.f) ? 1.f : 0.f;
    float mk1 = (em.y >= 0.f) ? 1.f : 0.f;
    float acc0 = 0.f, acc1 = 0.f;
#pragma unroll 8
    for (int c = 0; c < 64; c += 4) {
      float4 r  = *(const float4*)&xr[c];
      float4 l0 = *(const float4*)&xa[c];
      float4 l1 = *(const float4*)&xa[c + 68];
      float4 we = *(const float4*)&ws[G1WE + c];
      float4 at = *(const float4*)&ws[G1ATT + c];
      acc0 = fmaf(lrelu(fmaf(em.x, we.x, r.x) + l0.x), at.x, acc0);
      acc1 = fmaf(lrelu(fmaf(em.y, we.x, r.x) + l1.x), at.x, acc1);
      acc0 = fmaf(lrelu(fmaf(em.x, we.y, r.y) + l0.y), at.y, acc0);
      acc1 = fmaf(lrelu(fmaf(em.y, we.y, r.y) + l1.y), at.y, acc1);
      acc0 = fmaf(lrelu(fmaf(em.x, we.z, r.z) + l0.z), at.z, acc0);
      acc1 = fmaf(lrelu(fmaf(em.y, we.z, r.z) + l1.z), at.z, acc1);
      acc0 = fmaf(lrelu(fmaf(em.x, we.w, r.w) + l0.w), at.w, acc0);
      acc1 = fmaf(lrelu(fmaf(em.y, we.w, r.w) + l1.w), at.w, acc1);
    }
    float e0 = (mk0 != 0.f) ? acc0 : -1e30f;
    float e1 = (mk1 != 0.f) ? acc1 : -1e30f;
    float m = fmaxf(e0, e1);
    m = fmaxf(m, __shfl_xor_sync(0xffffffffu, m, 1));
    m = fmaxf(m, __shfl_xor_sync(0xffffffffu, m, 2));
    float x0 = __expf(e0 - m), x1 = __expf(e1 - m);
    float sden = x0 + x1;
    sden += __shfl_xor_sync(0xffffffffu, sden, 1);
    sden += __shfl_xor_sync(0xffffffffu, sden, 2);
    float inv = 1.f / sden;
    *(float2*)&sc[SALPHA + 2*t] = make_float2(x0*inv*mk0, x1*inv*mk1);
  }
  __syncwarp();

  // ======== GAT1 aggregation -> h1 (into SXR), channel-pair float2 =============
#pragma unroll
  for (int u = 0; u < 2; u++) {
    float* sc = u ? sc1 : sc0;
    float2 acc[8];
    float2 b2 = *(const float2*)&ws[G1BIAS + 2*t];
#pragma unroll
    for (int i = 0; i < 8; i++) acc[i] = b2;
#pragma unroll
    for (int j = 0; j < 8; j += 2) {
      float2 xa = *(const float2*)&sc[SXL + j*68 + 2*t];
      float2 xb = *(const float2*)&sc[SXL + (j+1)*68 + 2*t];
#pragma unroll
      for (int i = 0; i < 8; i++) {
        float2 al = *(const float2*)&sc[SALPHA + i*8 + j];
        acc[i].x = fmaf(al.x, xa.x, fmaf(al.y, xb.x, acc[i].x));
        acc[i].y = fmaf(al.x, xa.y, fmaf(al.y, xb.y, acc[i].y));
      }
    }
    __syncwarp();
#pragma unroll
    for (int i = 0; i < 8; i++) {
      float2 h;
      h.x = fmaxf(acc[i].x, 0.f);
      h.y = fmaxf(acc[i].y, 0.f);
      *(float2*)&sc[SXR + i*68 + 2*t] = h;
    }
  }
  __syncwarp();

  // ================= GAT2 linear (64->3 xl2, xr2) =================
  if (t < 24) {
#pragma unroll
    for (int u = 0; u < 2; u++) {
      float* sc = u ? sc1 : sc0;
      float a1 = ws[G2BL4 + l3], a2 = ws[G2BR4 + l3];
      const float* h1p = sc + SXR + n3*68;
#pragma unroll
      for (int c = 0; c < 64; c += 4) {
        float4 hh = *(const float4*)&h1p[c];
        float4 wl = *(const float4*)&ws[G2WLT + l3*64 + c];
        float4 wr = *(const float4*)&ws[G2WRT + l3*64 + c];
        a1 = fmaf(hh.x, wl.x, fmaf(hh.y, wl.y, fmaf(hh.z, wl.z, fmaf(hh.w, wl.w, a1))));
        a2 = fmaf(hh.x, wr.x, fmaf(hh.y, wr.y, fmaf(hh.z, wr.z, fmaf(hh.w, wr.w, a2))));
      }
      sc[SXL2 + n3*4 + l3] = a1;
      sc[SXR2 + n3*4 + l3] = a2;
    }
  }
  __syncwarp();

  // ================= GAT2 edge scores + softmax =================
#pragma unroll
  for (int u = 0; u < 2; u++) {
    float* sc = u ? sc1 : sc0;
    const int i = t >> 2;
    const int jj = (t & 3) * 2;
    float4 r   = *(const float4*)&sc[SXR2 + i*4];
    float4 l0  = *(const float4*)&sc[SXL2 + jj*4];
    float4 l1  = *(const float4*)&sc[SXL2 + (jj+1)*4];
    float4 we  = *(const float4*)&ws[G2WE4];
    float4 at  = *(const float4*)&ws[G2ATT4];
    float2 em = *(const float2*)&sc[SEM + 2*t];
    float mk0 = (em.x >= 0.f) ? 1.f : 0.f;
    float mk1 = (em.y >= 0.f) ? 1.f : 0.f;
    float acc0 = 0.f, acc1 = 0.f;
    acc0 = fmaf(lrelu(fmaf(em.x, we.x, r.x) + l0.x), at.x, acc0);
    acc1 = fmaf(lrelu(fmaf(em.y, we.x, r.x) + l1.x), at.x, acc1);
    acc0 = fmaf(lrelu(fmaf(em.x, we.y, r.y) + l0.y), at.y, acc0);
    acc1 = fmaf(lrelu(fmaf(em.y, we.y, r.y) + l1.y), at.y, acc1);
    acc0 = fmaf(lrelu(fmaf(em.x, we.z, r.z) + l0.z), at.z, acc0);
    acc1 = fmaf(lrelu(fmaf(em.y, we.z, r.z) + l1.z), at.z, acc1);
    float e0 = (mk0 != 0.f) ? acc0 : -1e30f;
    float e1 = (mk1 != 0.f) ? acc1 : -1e30f;
    float m = fmaxf(e0, e1);
    m = fmaxf(m, __shfl_xor_sync(0xffffffffu, m, 1));
    m = fmaxf(m, __shfl_xor_sync(0xffffffffu, m, 2));
    float x0 = __expf(e0 - m), x1 = __expf(e1 - m);
    float sden = x0 + x1;
    sden += __shfl_xor_sync(0xffffffffu, sden, 1);
    sden += __shfl_xor_sync(0xffffffffu, sden, 2);
    float inv = 1.f / sden;
    *(float2*)&sc[SALPHA + 2*t] = make_float2(x0*inv*mk0, x1*inv*mk1);
  }
  __syncwarp();

  // ================= GAT2 aggregation + skip -> combined =================
  if (t < 24) {
#pragma unroll
    for (int u = 0; u < 2; u++) {
      float* sc = u ? sc1 : sc0;
      float acc = ws[G2BIAS4 + l3];
#pragma unroll
      for (int j = 0; j < 8; j++)
        acc = fmaf(sc[SALPHA + n3*8 + j], sc[SXL2 + j*4 + l3], acc);
      float4 la = *(const float4*)&sc[SLAT + n3*4];
      acc += fmaf(la.x, ws[SKW + l3],
             fmaf(la.y, ws[SKW + 3 + l3],
             fmaf(la.z, ws[SKW + 6 + l3], ws[SKB + l3])));
      sc[SCOMB + n3*4 + l3] = acc;
    }
  }
  __syncwarp();

  // ================= decoder L1 (3->64) =================
  {
    float w0a=ws[DW1+t],    w1a=ws[DW1+64+t],    w2a=ws[DW1+128+t],    ba=ws[DB1+t];
    float w0b=ws[DW1+t+32], w1b=ws[DW1+64+t+32], w2b=ws[DW1+128+t+32], bb=ws[DB1+t+32];
#pragma unroll
    for (int u = 0; u < 2; u++) {
      float* sc = u ? sc1 : sc0;
      float va[8], vb[8];
#pragma unroll
      for (int n = 0; n < 8; n++) {
        float4 cm = *(const float4*)&sc[SCOMB + n*4];
        va[n] = fmaxf(fmaf(cm.x, w0a, fmaf(cm.y, w1a, fmaf(cm.z, w2a, ba))), 0.f);
        vb[n] = fmaxf(fmaf(cm.x, w0b, fmaf(cm.y, w1b, fmaf(cm.z, w2b, bb))), 0.f);
      }
      *(float4*)&sc[SA + t*8]          = make_float4(va[0],va[1],va[2],va[3]);
      *(float4*)&sc[SA + t*8 + 4]      = make_float4(va[4],va[5],va[6],va[7]);
      *(float4*)&sc[SA + (t+32)*8]     = make_float4(vb[0],vb[1],vb[2],vb[3]);
      *(float4*)&sc[SA + (t+32)*8 + 4] = make_float4(vb[4],vb[5],vb[6],vb[7]);
    }
  }
  __syncwarp();

  // ================= decoder L2+L3 (dual-sample) =================
  mlp64_dual(sc0 + SA, sc1 + SA, sc0, sc1, ws + DW2P, ws + DB2P, ws + DW3P, t);

#pragma unroll
  for (int u = 0; u < 2; u++) {
    float* sc = u ? sc1 : sc0;
    const bool vU = u ? v1 : v0;
    const int sU = u ? s1 : s0;
    if (vU && t < 24)
      out[Btot*24 + sU*24 + t] = sc[SLATP + t] + ws[DB3 + l3];
  }
}

extern "C" void kernel_launch(void* const* d_in, const int* in_sizes, int n_in,
                              void* d_out, int out_size)
{
  (void)n_in; (void)out_size;
  KParams kp;
  kp.x = (const float*)d_in[0];
  for (int i = 0; i < 28; i++) kp.w[i] = (const float*)d_in[i + 1];
  kp.B = in_sizes[0] / 8;

  cudaFuncSetAttribute(gae10_kernel, cudaFuncAttributeMaxDynamicSharedMemorySize, SMEM_BYTES);
  int grid = (kp.B + SPB - 1) / SPB;
  gae10_kernel<<<grid, THREADS, SMEM_BYTES>>>(kp, (float*)d_out);
}